// round 1
// baseline (speedup 1.0000x reference)
#include <cuda_runtime.h>

// Full-image equivalence: the tile/crop/stitch pipeline == running both convs
// once on the whole 2304x2304 image (SAME pad: lo=0, hi=1 for k=3,s=2,even in).
//
// conv1: int32 img [2304,2304,3] /255 -> [1152,1152,64] fp32 (NHWC scratch)
// conv2: [1152,1152,64] -> [576,576,128] -> written NCHW to d_out.

#define IMG 2304
#define H1  1152
#define H2  576
#define C1  64
#define C2  128

#define ROWW  33
#define PLANE (17 * ROWW)   // 561 (odd -> conflict-free ci-plane stride)

// 340 MB scratch for conv1 output, [y][x][ci] layout (ci contiguous).
__device__ float g_conv1[(size_t)H1 * H1 * C1];

// ---------- packed f32x2 helpers (Blackwell FFMA2 path) ----------
__device__ __forceinline__ unsigned long long pk2(float x, float y) {
    unsigned long long r;
    asm("mov.b64 %0, {%1, %2};" : "=l"(r) : "f"(x), "f"(y));
    return r;
}
__device__ __forceinline__ void upk2(unsigned long long v, float& x, float& y) {
    asm("mov.b64 {%0, %1}, %2;" : "=f"(x), "=f"(y) : "l"(v));
}
__device__ __forceinline__ void fma2(unsigned long long& d,
                                     unsigned long long a,
                                     unsigned long long b) {
    asm("fma.rn.f32x2 %0, %1, %2, %0;" : "+l"(d) : "l"(a), "l"(b));
}

// ============================ conv1 =================================
// Block: 256 threads (8 warps). Tile: 8 rows x 16 cols of conv1 output.
// warp -> row, lane -> co (co = lane and lane+32), 8 pixel-pairs/thread.
__global__ __launch_bounds__(256) void conv1_kernel(
    const int* __restrict__ img,
    const float* __restrict__ W1,
    const float* __restrict__ b1)
{
    __shared__ float s_in[3 * PLANE];                 // [c][17][33]
    __shared__ unsigned long long s_w[27 * 64];       // dup-packed weights
    __shared__ float s_b[64];

    const int t = threadIdx.x;
    const int lane = t & 31;
    const int w = t >> 5;
    const int x0 = blockIdx.x * 16;
    const int y0 = blockIdx.y * 8;

    // Stage weights as (w,w) pairs. W1 linear: ((ky*3+kx)*3+ci)*64+co.
    for (int i = t; i < 27 * 64; i += 256) {
        float v = W1[i];
        s_w[i] = pk2(v, v);
    }
    if (t < 64) s_b[t] = b1[t];

    // Stage normalized input tile: rows 2*y0..+16, cols 2*x0..+32, c=0..2.
    for (int i = t; i < 17 * 33 * 3; i += 256) {
        int c = i % 3;
        int pos = i / 3;
        int x = pos % 33;
        int y = pos / 33;
        int yin = 2 * y0 + y, xin = 2 * x0 + x;
        float v = 0.f;
        if (yin < IMG && xin < IMG)
            v = (float)img[(yin * IMG + xin) * 3 + c] * (1.f / 255.f);
        s_in[c * PLANE + y * ROWW + x] = v;
    }
    __syncthreads();

    const float bb0 = s_b[lane];
    const float bb1 = s_b[lane + 32];
    unsigned long long acc0[8], acc1[8];
#pragma unroll
    for (int j = 0; j < 8; j++) {
        acc0[j] = pk2(bb0, bb0);
        acc1[j] = pk2(bb1, bb1);
    }

#pragma unroll
    for (int kk = 0; kk < 9; kk++) {
        const int ky = kk / 3, kx = kk - ky * 3;
#pragma unroll
        for (int ci = 0; ci < 3; ci++) {
            const float* row = &s_in[ci * PLANE + (2 * w + ky) * ROWW + kx];
            const unsigned long long wv0 = s_w[(kk * 3 + ci) * 64 + lane];
            const unsigned long long wv1 = s_w[(kk * 3 + ci) * 64 + lane + 32];
#pragma unroll
            for (int j = 0; j < 8; j++) {
                unsigned long long v = pk2(row[4 * j], row[4 * j + 2]);
                fma2(acc0[j], v, wv0);
                fma2(acc1[j], v, wv1);
            }
        }
    }

    // Store ReLU'd results, coalesced over co.
    const int y = y0 + w;
#pragma unroll
    for (int j = 0; j < 8; j++) {
        const int x = x0 + 2 * j;
        const int pix = (y * H1 + x) * C1;
        float a, b;
        upk2(acc0[j], a, b);
        g_conv1[pix + lane]          = fmaxf(a, 0.f);
        g_conv1[pix + C1 + lane]     = fmaxf(b, 0.f);
        upk2(acc1[j], a, b);
        g_conv1[pix + lane + 32]      = fmaxf(a, 0.f);
        g_conv1[pix + C1 + lane + 32] = fmaxf(b, 0.f);
    }
}

// ============================ conv2 =================================
// Block: 256 threads (8 warps). Tile: 8 rows x 16 cols of conv2 output,
// all 128 co. warp -> row, lane -> co (4 co/thread), 8 pixel-pairs/thread.
// Dynamic smem: input [64][17][33] fp32 (143.6 KB) + dup weights 64x128
// float2 (64 KB) = 209,152 B. Output transposed through smem for coalesced
// NCHW stores.
#define SMEM2 (64 * PLANE * 4 + 64 * 128 * 8)

__global__ __launch_bounds__(256) void conv2_kernel(
    const float* __restrict__ W2,
    const float* __restrict__ b2,
    float* __restrict__ out)
{
    extern __shared__ float smem[];
    float* s_in = smem;                                            // 64*561 floats
    unsigned long long* s_w = (unsigned long long*)(smem + 64 * PLANE); // 8192 ull
    float* s_out = smem;                                           // overlay after loop

    const int t = threadIdx.x;
    const int lane = t & 31;
    const int w = t >> 5;
    const int x0 = blockIdx.x * 16;
    const int y0 = blockIdx.y * 8;

    // Stage input tile: lane->ci gives coalesced global reads; odd plane
    // stride (561) gives conflict-free STS.
    for (int i = t; i < 64 * 17 * 33; i += 256) {
        int ci = i & 63;
        int pos = i >> 6;
        int x = pos % 33;
        int y = pos / 33;
        int yin = 2 * y0 + y, xin = 2 * x0 + x;
        float v = 0.f;
        if (yin < H1 && xin < H1)
            v = g_conv1[(yin * H1 + xin) * C1 + ci];
        s_in[ci * PLANE + y * ROWW + x] = v;
    }

    unsigned long long acc[4][8];
#pragma unroll
    for (int c = 0; c < 4; c++) {
        float bv = b2[lane + 32 * c];
#pragma unroll
        for (int j = 0; j < 8; j++) acc[c][j] = pk2(bv, bv);
    }

    for (int kk = 0; kk < 9; kk++) {
        __syncthreads();  // input staged (kk=0) / previous phase consumers done
        // Stage dup-packed weight slice [64][128] for this (ky,kx).
        const float* wg = W2 + kk * 64 * 128;
        for (int i = t; i < 64 * 128; i += 256) {
            float v = wg[i];
            s_w[i] = pk2(v, v);
        }
        __syncthreads();

        const int ky = kk / 3, kx = kk - ky * 3;
        const float* rowp = &s_in[(2 * w + ky) * ROWW + kx];
#pragma unroll 4
        for (int ci = 0; ci < 64; ci++) {
            const float* row = rowp + ci * PLANE;
            unsigned long long vv[8];
#pragma unroll
            for (int j = 0; j < 8; j++)
                vv[j] = pk2(row[4 * j], row[4 * j + 2]);
#pragma unroll
            for (int c = 0; c < 4; c++) {
                const unsigned long long wv = s_w[ci * 128 + lane + 32 * c];
#pragma unroll
                for (int j = 0; j < 8; j++) fma2(acc[c][j], vv[j], wv);
            }
        }
    }
    __syncthreads();

    // Transpose through smem: s_out[co][129] (odd stride -> conflict-free).
#pragma unroll
    for (int c = 0; c < 4; c++) {
        const int co = lane + 32 * c;
#pragma unroll
        for (int j = 0; j < 8; j++) {
            float a, b;
            upk2(acc[c][j], a, b);
            s_out[co * 129 + w * 16 + 2 * j]     = fmaxf(a, 0.f);
            s_out[co * 129 + w * 16 + 2 * j + 1] = fmaxf(b, 0.f);
        }
    }
    __syncthreads();

    // Coalesced NCHW stores: 16 consecutive x per (co,y) row segment.
    for (int e = t; e < 128 * 128; e += 256) {
        int co = e >> 7;
        int p = e & 127;
        int y = y0 + (p >> 4);
        int x = x0 + (p & 15);
        out[(co * H2 + y) * H2 + x] = s_out[co * 129 + p];
    }
}

// ============================ launch ================================
extern "C" void kernel_launch(void* const* d_in, const int* in_sizes, int n_in,
                              void* d_out, int out_size)
{
    const int*   img = (const int*)d_in[0];
    const float* W1  = (const float*)d_in[1];
    const float* b1  = (const float*)d_in[2];
    const float* W2  = (const float*)d_in[3];
    const float* b2  = (const float*)d_in[4];
    float* out = (float*)d_out;

    // Idempotent, not a stream op — safe under graph capture.
    cudaFuncSetAttribute(conv2_kernel,
                         cudaFuncAttributeMaxDynamicSharedMemorySize, SMEM2);

    conv1_kernel<<<dim3(H1 / 16, H1 / 8), 256>>>(img, W1, b1);
    conv2_kernel<<<dim3(H2 / 16, H2 / 8), 256, SMEM2>>>(W2, b2, out);
}

// round 2
// speedup vs baseline: 1.2044x; 1.2044x over previous
#include <cuda_runtime.h>

// Full-image equivalence of the tile/crop/stitch pipeline (pad lo=0, hi=1).
// conv1: int32 img [2304,2304,3]/255 -> [1152,1152,64] fp32 NHWC scratch
// conv2: [1152,1152,64] -> [576,576,128] NCHW fp32 out.
//
// Both convs use packed fma.rn.f32x2 (FFMA2), pairing adjacent output pixels.
// conv2: 512 threads, 8x16 output tile, ci-split across warp halves.

#define IMG 2304
#define H1  1152
#define H2  576
#define C1  64

// conv2 smem geometry: row stride 36 floats (144B, 16B-aligned), 17 rows.
#define ROWW   36
#define PLANE  (17 * ROWW)          // 612 floats per ci plane (16B aligned)
// conv1 smem geometry: 33 rows of 36.
#define PLANE1 (33 * ROWW)          // 1188

__device__ float g_conv1[(size_t)H1 * H1 * C1];

typedef unsigned long long u64;

__device__ __forceinline__ u64 pk2(float x, float y) {
    u64 r; asm("mov.b64 %0, {%1, %2};" : "=l"(r) : "f"(x), "f"(y)); return r;
}
__device__ __forceinline__ void upk2(u64 v, float& x, float& y) {
    asm("mov.b64 {%0, %1}, %2;" : "=f"(x), "=f"(y) : "l"(v));
}
__device__ __forceinline__ void fma2(u64& d, u64 a, u64 b) {
    asm("fma.rn.f32x2 %0, %1, %2, %0;" : "+l"(d) : "l"(a), "l"(b));
}
__device__ __forceinline__ u64 add2(u64 a, u64 b) {
    u64 r; asm("add.rn.f32x2 %0, %1, %2;" : "=l"(r) : "l"(a), "l"(b)); return r;
}

// ---- conv2 inner pass: 32 ci for one (ky,kx), KX compile-time ----
template <int KX>
__device__ __forceinline__ void conv2_pass(
    const float* __restrict__ rowbase,      // s_in + (2r+ky)*ROWW
    const u64* __restrict__ s_w,            // dup-packed [64][128]
    int ci0, int lane, u64 acc[4][8])
{
#pragma unroll 4
    for (int ci = ci0; ci < ci0 + 32; ci++) {
        const float4* v4 = (const float4*)(rowbase + ci * PLANE);
        float4 v[9];
#pragma unroll
        for (int j = 0; j < 8; j++) v[j] = v4[j];
        if (KX == 2) v[8] = v4[8];
        u64 p[8];
#pragma unroll
        for (int j = 0; j < 8; j++) {
            if (KX == 0) p[j] = pk2(v[j].x, v[j].z);
            if (KX == 1) p[j] = pk2(v[j].y, v[j].w);
            if (KX == 2) p[j] = pk2(v[j].z, v[j + 1].x);
        }
        const u64* wrow = s_w + ci * 128 + lane;
#pragma unroll
        for (int c = 0; c < 4; c++) {
            const u64 wv = wrow[32 * c];
#pragma unroll
            for (int j = 0; j < 8; j++) fma2(acc[c][j], p[j], wv);
        }
    }
}

#define SMEM2 (C1 * PLANE * 4 + C1 * 128 * 8)   // 156672 + 65536 = 222208 B

__global__ __launch_bounds__(512) void conv2_kernel(
    const float* __restrict__ W2,
    const float* __restrict__ b2,
    float* __restrict__ out)
{
    extern __shared__ float smem[];
    float* s_in = smem;                                   // [64][17][36]
    u64*   s_w  = (u64*)(smem + C1 * PLANE);              // [64][128] dup pairs
    float* s_out = smem;                                  // overlay after loop

    const int t    = threadIdx.x;
    const int lane = t & 31;
    const int w    = t >> 5;        // 0..15
    const int r    = w & 7;         // output row within tile
    const int h    = w >> 3;        // ci half
    const int x0   = blockIdx.x * 16;
    const int y0   = blockIdx.y * 8;

    // Stage input tile rows 2*y0..+16, cols 2*x0..+32 (lane->ci coalesced).
    for (int i = t; i < C1 * 17 * 33; i += 512) {
        int ci = i & 63;
        int pos = i >> 6;
        int x = pos % 33;
        int y = pos / 33;
        int yin = 2 * y0 + y, xin = 2 * x0 + x;
        float v = 0.f;
        if (yin < H1 && xin < H1)
            v = g_conv1[((size_t)yin * H1 + xin) * C1 + ci];
        s_in[ci * PLANE + y * ROWW + x] = v;
    }

    u64 acc[4][8];
#pragma unroll
    for (int c = 0; c < 4; c++) {
        float bv = (h == 0) ? b2[lane + 32 * c] : 0.f;
#pragma unroll
        for (int j = 0; j < 8; j++) acc[c][j] = pk2(bv, bv);
    }

    const int ci0 = 32 * h;
    for (int kk = 0; kk < 9; kk++) {
        __syncthreads();
        const float* wg = W2 + kk * C1 * 128;
        for (int i = t; i < C1 * 128; i += 512) {
            float v = wg[i];
            s_w[i] = pk2(v, v);
        }
        __syncthreads();

        const int ky = kk / 3, kx = kk - ky * 3;
        const float* rowbase = s_in + (2 * r + ky) * ROWW;
        if      (kx == 0) conv2_pass<0>(rowbase, s_w, ci0, lane, acc);
        else if (kx == 1) conv2_pass<1>(rowbase, s_w, ci0, lane, acc);
        else              conv2_pass<2>(rowbase, s_w, ci0, lane, acc);
    }
    __syncthreads();

    // Cross-half reduction through the weight smem region (8192 u64).
    u64* s_red = s_w;
    if (h == 1) {
        const int b = t & 255;
#pragma unroll
        for (int c = 0; c < 4; c++)
#pragma unroll
            for (int j = 0; j < 8; j++)
                s_red[(c * 8 + j) * 256 + b] = acc[c][j];
    }
    __syncthreads();
    if (h == 0) {
#pragma unroll
        for (int c = 0; c < 4; c++)
#pragma unroll
            for (int j = 0; j < 8; j++)
                acc[c][j] = add2(acc[c][j], s_red[(c * 8 + j) * 256 + t]);
    }
    __syncthreads();   // s_in reads done everywhere; safe to overlay s_out

    if (h == 0) {
#pragma unroll
        for (int c = 0; c < 4; c++) {
            const int co = lane + 32 * c;
#pragma unroll
            for (int j = 0; j < 8; j++) {
                float a, b;
                upk2(acc[c][j], a, b);
                s_out[co * 129 + r * 16 + 2 * j]     = fmaxf(a, 0.f);
                s_out[co * 129 + r * 16 + 2 * j + 1] = fmaxf(b, 0.f);
            }
        }
    }
    __syncthreads();

    // Coalesced NCHW stores.
    for (int e = t; e < 128 * 128; e += 512) {
        int co = e >> 7;
        int p = e & 127;
        int y = y0 + (p >> 4);
        int x = x0 + (p & 15);
        out[((size_t)co * H2 + y) * H2 + x] = s_out[co * 129 + p];
    }
}

// ============================ conv1 =================================
// 512 threads, 16x16 output tile, warp -> row, lane -> co (+32).
template <int KX>
__device__ __forceinline__ void conv1_pass(
    const float* __restrict__ rowbase,
    const u64* __restrict__ s_w,   // dup pairs [kk*3+ci][64]
    int kk, int lane, u64 acc0[8], u64 acc1[8])
{
#pragma unroll
    for (int ci = 0; ci < 3; ci++) {
        const float4* v4 = (const float4*)(rowbase + ci * PLANE1);
        float4 v[9];
#pragma unroll
        for (int j = 0; j < 8; j++) v[j] = v4[j];
        if (KX == 2) v[8] = v4[8];
        u64 p[8];
#pragma unroll
        for (int j = 0; j < 8; j++) {
            if (KX == 0) p[j] = pk2(v[j].x, v[j].z);
            if (KX == 1) p[j] = pk2(v[j].y, v[j].w);
            if (KX == 2) p[j] = pk2(v[j].z, v[j + 1].x);
        }
        const u64 wv0 = s_w[(kk * 3 + ci) * 64 + lane];
        const u64 wv1 = s_w[(kk * 3 + ci) * 64 + lane + 32];
#pragma unroll
        for (int j = 0; j < 8; j++) {
            fma2(acc0[j], p[j], wv0);
            fma2(acc1[j], p[j], wv1);
        }
    }
}

__global__ __launch_bounds__(512) void conv1_kernel(
    const int* __restrict__ img,
    const float* __restrict__ W1,
    const float* __restrict__ b1)
{
    __shared__ float s_in[3 * PLANE1];      // [3][33][36]
    __shared__ u64   s_w[27 * 64];
    __shared__ float s_b[64];

    const int t    = threadIdx.x;
    const int lane = t & 31;
    const int w    = t >> 5;               // 0..15 -> output row
    const int x0   = blockIdx.x * 16;
    const int y0   = blockIdx.y * 16;

    for (int i = t; i < 27 * 64; i += 512) {
        float v = W1[i];
        s_w[i] = pk2(v, v);
    }
    if (t < 64) s_b[t] = b1[t];

    for (int i = t; i < 33 * 33 * 3; i += 512) {
        int c = i % 3;
        int pos = i / 3;
        int x = pos % 33;
        int y = pos / 33;
        int yin = 2 * y0 + y, xin = 2 * x0 + x;
        float v = 0.f;
        if (yin < IMG && xin < IMG)
            v = (float)img[((size_t)yin * IMG + xin) * 3 + c] * (1.f / 255.f);
        s_in[c * PLANE1 + y * ROWW + x] = v;
    }
    __syncthreads();

    const float bb0 = s_b[lane];
    const float bb1 = s_b[lane + 32];
    u64 acc0[8], acc1[8];
#pragma unroll
    for (int j = 0; j < 8; j++) {
        acc0[j] = pk2(bb0, bb0);
        acc1[j] = pk2(bb1, bb1);
    }

#pragma unroll
    for (int kk = 0; kk < 9; kk++) {
        const int ky = kk / 3, kx = kk - ky * 3;
        const float* rowbase = s_in + (2 * w + ky) * ROWW;
        if      (kx == 0) conv1_pass<0>(rowbase, s_w, kk, lane, acc0, acc1);
        else if (kx == 1) conv1_pass<1>(rowbase, s_w, kk, lane, acc0, acc1);
        else              conv1_pass<2>(rowbase, s_w, kk, lane, acc0, acc1);
    }

    const int y = y0 + w;
#pragma unroll
    for (int j = 0; j < 8; j++) {
        const int x = x0 + 2 * j;
        const size_t pix = ((size_t)y * H1 + x) * C1;
        float a, b;
        upk2(acc0[j], a, b);
        g_conv1[pix + lane]           = fmaxf(a, 0.f);
        g_conv1[pix + C1 + lane]      = fmaxf(b, 0.f);
        upk2(acc1[j], a, b);
        g_conv1[pix + lane + 32]      = fmaxf(a, 0.f);
        g_conv1[pix + C1 + lane + 32] = fmaxf(b, 0.f);
    }
}

// ============================ launch ================================
extern "C" void kernel_launch(void* const* d_in, const int* in_sizes, int n_in,
                              void* d_out, int out_size)
{
    const int*   img = (const int*)d_in[0];
    const float* W1  = (const float*)d_in[1];
    const float* b1  = (const float*)d_in[2];
    const float* W2  = (const float*)d_in[3];
    const float* b2  = (const float*)d_in[4];
    float* out = (float*)d_out;

    cudaFuncSetAttribute(conv2_kernel,
                         cudaFuncAttributeMaxDynamicSharedMemorySize, SMEM2);

    conv1_kernel<<<dim3(H1 / 16, H1 / 16), 512>>>(img, W1, b1);
    conv2_kernel<<<dim3(H2 / 16, H2 / 8), 512, SMEM2>>>(W2, b2, out);
}

// round 4
// speedup vs baseline: 4.7476x; 3.9419x over previous
#include <cuda_runtime.h>
#include <cuda_fp16.h>
#include <cstdint>

// conv1: FFMA2 fp32, de-interleaved smem -> fp16 NHWC scratch [1152,1152,64]
// conv2: legacy HMMA mma.sync.m16n8k16 (f16 in, f32 acc) -> [128,576,576] NCHW
// Full-image equivalence of the tile/crop/stitch pipeline (pad lo=0, hi=1).
// NOTE: tcgen05.* readback path (tcgen05.ld/wait/dealloc) is rejected by this
// toolchain's sm_103 family target -- mma.sync/ldmatrix are family-safe.

#define IMG 2304
#define H1  1152
#define H2  576
#define C1  64

typedef unsigned long long u64;

__device__ __half g_conv1h[(size_t)H1 * H1 * C1];   // 170 MB fp16 scratch
__device__ __half g_w2t[9 * 128 * 64];              // [kk][n][k] fp16, SW128-baked

// ---------------- packed f32x2 helpers (conv1) ----------------
__device__ __forceinline__ u64 pk2(float x, float y) {
    u64 r; asm("mov.b64 %0, {%1, %2};" : "=l"(r) : "f"(x), "f"(y)); return r;
}
__device__ __forceinline__ void upk2(u64 v, float& x, float& y) {
    asm("mov.b64 {%0, %1}, %2;" : "=f"(x), "=f"(y) : "l"(v));
}
__device__ __forceinline__ void fma2(u64& d, u64 a, u64 b) {
    asm("fma.rn.f32x2 %0, %1, %2, %0;" : "+l"(d) : "l"(a), "l"(b));
}

// ---------------- HMMA helpers ----------------
__device__ __forceinline__ uint32_t smem_u32(const void* p) {
    uint32_t a;
    asm("{ .reg .u64 t; cvta.to.shared.u64 t, %1; cvt.u32.u64 %0, t; }"
        : "=r"(a) : "l"(p));
    return a;
}
__device__ __forceinline__ void ldsm4(uint32_t (&r)[4], uint32_t addr) {
    asm volatile("ldmatrix.sync.aligned.m8n8.x4.shared.b16 {%0,%1,%2,%3}, [%4];"
        : "=r"(r[0]), "=r"(r[1]), "=r"(r[2]), "=r"(r[3]) : "r"(addr));
}
__device__ __forceinline__ void mma16816(float (&d)[4], const uint32_t (&a)[4],
                                         uint32_t b0, uint32_t b1) {
    asm volatile(
        "mma.sync.aligned.m16n8k16.row.col.f32.f16.f16.f32 "
        "{%0,%1,%2,%3}, {%4,%5,%6,%7}, {%8,%9}, {%0,%1,%2,%3};"
        : "+f"(d[0]), "+f"(d[1]), "+f"(d[2]), "+f"(d[3])
        : "r"(a[0]), "r"(a[1]), "r"(a[2]), "r"(a[3]), "r"(b0), "r"(b1));
}
#define CP16(dst, src) \
    asm volatile("cp.async.ca.shared.global [%0], [%1], 16;" :: "r"(dst), "l"(src))
#define CP_COMMIT() asm volatile("cp.async.commit_group;" ::: "memory")
#define CP_WAIT0()  asm volatile("cp.async.wait_group 0;" ::: "memory")

// ======================= prep: W2 -> fp16 [kk][n][k], swizzle baked =======================
__global__ void prep_w2_kernel(const float* __restrict__ W2) {
    int i = blockIdx.x * 256 + threadIdx.x;            // 9*128*64
    if (i >= 9 * 128 * 64) return;
    int ci = i & 63;
    int n  = (i >> 6) & 127;
    int kk = i >> 13;
    float v = W2[(kk * 64 + ci) * 128 + n];
    int j = ci >> 3;                                   // 16B chunk within 128B row
    int hidx = n * 64 + ((j ^ (n & 7)) << 3) + (ci & 7);
    g_w2t[kk * 8192 + hidx] = __float2half_rn(v);
}

// ======================= conv1 (FFMA2, fp16 out) =======================
#define C1ROW  52                 // even[0..16] odd@20[..35] evenShift@36[..51]
#define PLANE1 (33 * C1ROW)

__global__ __launch_bounds__(512) void conv1_kernel(
    const int* __restrict__ img,
    const float* __restrict__ W1,
    const float* __restrict__ b1)
{
    __shared__ float s_in[3 * PLANE1];
    __shared__ u64   s_w[27 * 64];
    __shared__ float s_b[64];

    const int t    = threadIdx.x;
    const int lane = t & 31;
    const int w    = t >> 5;               // 0..15 -> output row
    const int x0   = blockIdx.x * 16;
    const int y0   = blockIdx.y * 16;

    for (int i = t; i < 27 * 64; i += 512) {
        float v = W1[i];
        s_w[i] = pk2(v, v);
    }
    if (t < 64) s_b[t] = b1[t];

    for (int i = t; i < 33 * 33 * 3; i += 512) {
        int c = i % 3;
        int pos = i / 3;
        int x = pos % 33;
        int y = pos / 33;
        int yin = 2 * y0 + y, xin = 2 * x0 + x;
        float v = 0.f;
        if (yin < IMG && xin < IMG)
            v = (float)img[((size_t)yin * IMG + xin) * 3 + c] * (1.f / 255.f);
        float* rb = s_in + c * PLANE1 + y * C1ROW;
        if (x & 1) {
            rb[20 + (x >> 1)] = v;
        } else {
            int h = x >> 1;
            rb[h] = v;
            if (h >= 1) rb[36 + h - 1] = v;
        }
    }
    __syncthreads();

    const float bb0 = s_b[lane];
    const float bb1 = s_b[lane + 32];
    u64 acc0[8], acc1[8];
#pragma unroll
    for (int j = 0; j < 8; j++) {
        acc0[j] = pk2(bb0, bb0);
        acc1[j] = pk2(bb1, bb1);
    }

#define DO_KX(V, widx) {                                                     \
    const u64 wv0 = s_w[(widx) * 64 + lane];                                 \
    const u64 wv1 = s_w[(widx) * 64 + lane + 32];                            \
    _Pragma("unroll")                                                        \
    for (int k = 0; k < 4; k++) {                                            \
        u64 p0 = pk2(V[k].x, V[k].y);                                        \
        u64 p1 = pk2(V[k].z, V[k].w);                                        \
        fma2(acc0[2 * k],     p0, wv0);                                      \
        fma2(acc1[2 * k],     p0, wv1);                                      \
        fma2(acc0[2 * k + 1], p1, wv0);                                      \
        fma2(acc1[2 * k + 1], p1, wv1);                                      \
    } }

#pragma unroll
    for (int ky = 0; ky < 3; ky++) {
#pragma unroll
        for (int ci = 0; ci < 3; ci++) {
            const float* rb = s_in + ci * PLANE1 + (2 * w + ky) * C1ROW;
            float4 E[4], O[4], S[4];
#pragma unroll
            for (int k = 0; k < 4; k++) {
                E[k] = ((const float4*)rb)[k];
                O[k] = ((const float4*)(rb + 20))[k];
                S[k] = ((const float4*)(rb + 36))[k];
            }
            DO_KX(E, (ky * 3 + 0) * 3 + ci);
            DO_KX(O, (ky * 3 + 1) * 3 + ci);
            DO_KX(S, (ky * 3 + 2) * 3 + ci);
        }
    }

    const int y = y0 + w;
#pragma unroll
    for (int j = 0; j < 8; j++) {
        size_t p0 = ((size_t)y * H1 + x0 + 2 * j) * C1;
        float a, b;
        upk2(acc0[j], a, b);
        g_conv1h[p0 + lane]      = __float2half_rn(fmaxf(a, 0.f));
        g_conv1h[p0 + C1 + lane] = __float2half_rn(fmaxf(b, 0.f));
        upk2(acc1[j], a, b);
        g_conv1h[p0 + lane + 32]      = __float2half_rn(fmaxf(a, 0.f));
        g_conv1h[p0 + C1 + lane + 32] = __float2half_rn(fmaxf(b, 0.f));
    }
}

// ======================= conv2 (HMMA) =======================
// 256 threads / 8 warps. Output tile: M=128 pixels (8y x 16x), N=128 co.
// Warp grid 4x2: wm -> 32 pixels (y=2wm,2wm+1), wn -> 64 co.
// smem layout (bytes):
//   [0,512)          bias (128 f32)
//   [512,37504)      IN_E: even-x pixels [17y][17xe][64ci] fp16, SW128
//   [37504,72320)    IN_O: odd-x  pixels [17y][16xo][64ci] fp16, SW128
//   [72320,105088)   B double buffer, 2 x 16KB ([n][k] fp16, SW128)
//   s_out overlay at 512 after the K loop (128co x 130 f32).
#define IN_E  512
#define IN_O  (IN_E + 17 * 17 * 128)    // 37504
#define B_OFF (IN_O + 17 * 16 * 128)    // 72320
#define SMEM2 (B_OFF + 2 * 16384)       // 105088

__global__ __launch_bounds__(256, 2) void conv2_kernel(
    const float* __restrict__ b2,
    float* __restrict__ out)
{
    extern __shared__ __align__(128) char smem[];
    const uint32_t sb = smem_u32(smem);

    const int t    = threadIdx.x;
    const int lane = t & 31;
    const int wid  = t >> 5;
    const int wm   = wid & 3;
    const int wn   = wid >> 2;
    const int x0   = blockIdx.x * 16;
    const int y0   = blockIdx.y * 8;

    if (t < 128) ((float*)smem)[t] = b2[t];

    // Stage B0 (pre-swizzled in gmem -> straight copy) via cp.async.
    for (int i = t; i < 1024; i += 256)
        CP16(sb + B_OFF + i * 16, (const char*)g_w2t + i * 16);
    CP_COMMIT();

    // Stage input patch, de-interleaved by x parity, SW128 swizzle.
    for (int i = t; i < 17 * 33 * 8; i += 256) {
        int j = i & 7, pix = i >> 3;
        int xl = pix % 33, yl = pix / 33;
        int yin = 2 * y0 + yl, xin = 2 * x0 + xl;
        uint4 v = make_uint4(0, 0, 0, 0);
        if (yin < H1 && xin < H1)
            v = *(const uint4*)(g_conv1h + ((size_t)yin * H1 + xin) * C1 + j * 8);
        int arr, p;
        if (xl & 1) { arr = IN_O; p = yl * 16 + (xl >> 1); }
        else        { arr = IN_E; p = yl * 17 + (xl >> 1); }
        *(uint4*)(smem + arr + p * 128 + ((j ^ (p & 7)) << 4)) = v;
    }
    CP_WAIT0();
    __syncthreads();

    float d[2][8][4];
#pragma unroll
    for (int i = 0; i < 2; i++)
#pragma unroll
        for (int j = 0; j < 8; j++)
#pragma unroll
            for (int q = 0; q < 4; q++) d[i][j][q] = 0.f;

    // Lane constants for ldmatrix addressing.
    const int xa = lane & 15;            // A pixel row within m16 tile
    const int ca = lane >> 4;            // A chunk select
    const int nb = (lane & 7) + ((lane >> 4) << 3);   // B row within 16-n group
    const int cb = (lane >> 3) & 1;      // B chunk select
    const int eB = lane & 7;             // B swizzle key ((64wn+16u+nb)&7 == lane&7)
    uint32_t qB[4];
#pragma unroll
    for (int u = 0; u < 4; u++)
        qB[u] = sb + B_OFF + (uint32_t)(64 * wn + 16 * u + nb) * 128;

    for (int kk = 0; kk < 9; kk++) {
        if (kk < 8) {   // prefetch next B tile into the other buffer
            const char* src = (const char*)(g_w2t + (kk + 1) * 8192);
            uint32_t dstb = sb + B_OFF + (uint32_t)(((kk + 1) & 1) << 14);
            for (int i = t; i < 1024; i += 256)
                CP16(dstb + i * 16, src + i * 16);
            CP_COMMIT();
        }
        const int ky = kk / 3, kx = kk - ky * 3;
        uint32_t arr; int W, xoff;
        if (kx == 1) { arr = IN_O; W = 16; xoff = 0; }
        else         { arr = IN_E; W = 17; xoff = kx >> 1; }
        const int p0 = (4 * wm + ky) * W + xoff + xa;
        const int p1 = p0 + 2 * W;
        const uint32_t q0 = sb + arr + (uint32_t)p0 * 128;
        const uint32_t q1 = sb + arr + (uint32_t)p1 * 128;
        const int e0 = p0 & 7, e1 = p1 & 7;
        const uint32_t bufo = (uint32_t)((kk & 1) << 14);

#pragma unroll
        for (int s4 = 0; s4 < 4; s4++) {
            const int c = 2 * s4;
            uint32_t a0[4], a1[4];
            ldsm4(a0, q0 + (uint32_t)(((c + ca) ^ e0) << 4));
            ldsm4(a1, q1 + (uint32_t)(((c + ca) ^ e1) << 4));
            const uint32_t xb = (uint32_t)(((c + cb) ^ eB) << 4) + bufo;
#pragma unroll
            for (int u = 0; u < 4; u++) {
                uint32_t bb[4];
                ldsm4(bb, qB[u] + xb);
                mma16816(d[0][2 * u],     a0, bb[0], bb[1]);
                mma16816(d[0][2 * u + 1], a0, bb[2], bb[3]);
                mma16816(d[1][2 * u],     a1, bb[0], bb[1]);
                mma16816(d[1][2 * u + 1], a1, bb[2], bb[3]);
            }
        }
        if (kk < 8) CP_WAIT0();
        __syncthreads();
    }

    // Epilogue: transpose through smem (overlay on input region), bias+ReLU,
    // coalesced NCHW stores.
    float* s_out = (float*)(smem + IN_E);          // [128co][130]
    const int g  = lane >> 2;
    const int nq = (lane & 3) * 2;
#pragma unroll
    for (int ti = 0; ti < 2; ti++)
#pragma unroll
        for (int tj = 0; tj < 8; tj++)
#pragma unroll
            for (int rp = 0; rp < 2; rp++) {
                int m = 32 * wm + 16 * ti + g + 8 * rp;
                int n = 64 * wn + 8 * tj + nq;
                s_out[n * 130 + m]       = d[ti][tj][2 * rp];
                s_out[(n + 1) * 130 + m] = d[ti][tj][2 * rp + 1];
            }
    __syncthreads();

    const float* s_bias = (const float*)smem;
    for (int e = t; e < 128 * 128; e += 256) {
        int co = e >> 7, p = e & 127;
        int y = y0 + (p >> 4), x = x0 + (p & 15);
        float v = s_out[co * 130 + p] + s_bias[co];
        out[((size_t)co * H2 + y) * H2 + x] = fmaxf(v, 0.f);
    }
}

// ======================= launch =======================
extern "C" void kernel_launch(void* const* d_in, const int* in_sizes, int n_in,
                              void* d_out, int out_size)
{
    const int*   img = (const int*)d_in[0];
    const float* W1  = (const float*)d_in[1];
    const float* b1  = (const float*)d_in[2];
    const float* W2  = (const float*)d_in[3];
    const float* b2  = (const float*)d_in[4];
    float* out = (float*)d_out;

    cudaFuncSetAttribute(conv2_kernel,
                         cudaFuncAttributeMaxDynamicSharedMemorySize, SMEM2);

    prep_w2_kernel<<<(9 * 128 * 64 + 255) / 256, 256>>>(W2);
    conv1_kernel<<<dim3(H1 / 16, H1 / 16), 512>>>(img, W1, b1);
    conv2_kernel<<<dim3(H2 / 16, H2 / 8), 256, SMEM2>>>(b2, out);
}

// round 5
// speedup vs baseline: 4.9698x; 1.0468x over previous
#include <cuda_runtime.h>
#include <cuda_fp16.h>
#include <cstdint>

// Fully fused: image -> conv1 (FFMA2, fp32) -> smem fp16 tile -> conv2 (HMMA)
// -> NCHW out. No gmem scratch. Full-image equivalence of tile/crop/stitch.

#define IMG 2304
#define H2  576

typedef unsigned long long u64;

__device__ __half g_w2t[9 * 128 * 64];   // [kk][n=co][k=ci] fp16, SW128-baked
__device__ u64    g_w1d[27 * 64];        // conv1 weights dup-packed (w,w)

// smem layout (bytes)
#define INE_OFF 0                         // [33*17 rows][128B] fp16 SW128
#define INO_OFF 71808                     // [33*16 rows][128B]
#define IMG_OFF 139392                    // 3ch x 67rows x 72 f32 (E34|pad2|O34|pad2)
#define B_OFF   197280                    // B double buffer 2x16KB
#define SMEMT   230048
#define IROW    72
#define IPLANE  (72 * 67)

// ---------------- helpers ----------------
__device__ __forceinline__ u64 pk2(float x, float y) {
    u64 r; asm("mov.b64 %0, {%1, %2};" : "=l"(r) : "f"(x), "f"(y)); return r;
}
__device__ __forceinline__ void upk2(u64 v, float& x, float& y) {
    asm("mov.b64 {%0, %1}, %2;" : "=f"(x), "=f"(y) : "l"(v));
}
__device__ __forceinline__ void fma2(u64& d, u64 a, u64 b) {
    asm("fma.rn.f32x2 %0, %1, %2, %0;" : "+l"(d) : "l"(a), "l"(b));
}
__device__ __forceinline__ uint32_t cvtpack(float lo, float hi) {
    uint32_t r;
    asm("cvt.rn.f16x2.f32 %0, %1, %2;" : "=r"(r) : "f"(hi), "f"(lo));
    return r;
}
__device__ __forceinline__ uint32_t smem_u32(const void* p) {
    uint32_t a;
    asm("{ .reg .u64 t; cvta.to.shared.u64 t, %1; cvt.u32.u64 %0, t; }"
        : "=r"(a) : "l"(p));
    return a;
}
__device__ __forceinline__ void ldsm4(uint32_t (&r)[4], uint32_t addr) {
    asm volatile("ldmatrix.sync.aligned.m8n8.x4.shared.b16 {%0,%1,%2,%3}, [%4];"
        : "=r"(r[0]), "=r"(r[1]), "=r"(r[2]), "=r"(r[3]) : "r"(addr));
}
__device__ __forceinline__ void mma16816(float (&d)[4], const uint32_t (&a)[4],
                                         uint32_t b0, uint32_t b1) {
    asm volatile(
        "mma.sync.aligned.m16n8k16.row.col.f32.f16.f16.f32 "
        "{%0,%1,%2,%3}, {%4,%5,%6,%7}, {%8,%9}, {%0,%1,%2,%3};"
        : "+f"(d[0]), "+f"(d[1]), "+f"(d[2]), "+f"(d[3])
        : "r"(a[0]), "r"(a[1]), "r"(a[2]), "r"(a[3]), "r"(b0), "r"(b1));
}
#define CP16(dst, src) \
    asm volatile("cp.async.ca.shared.global [%0], [%1], 16;" :: "r"(dst), "l"(src))
#define CP_COMMIT() asm volatile("cp.async.commit_group;" ::: "memory")
#define CP_WAIT0()  asm volatile("cp.async.wait_group 0;" ::: "memory")

// ============ prep: W2 -> fp16 [kk][n][k] swizzled; W1 -> dup pairs ============
__global__ void prep_kernel(const float* __restrict__ W2,
                            const float* __restrict__ W1) {
    int i = blockIdx.x * 256 + threadIdx.x;
    if (i < 9 * 128 * 64) {
        int ci = i & 63, n = (i >> 6) & 127, kk = i >> 13;
        float v = W2[(kk * 64 + ci) * 128 + n];
        int j = ci >> 3;
        g_w2t[kk * 8192 + n * 64 + ((j ^ (n & 7)) << 3) + (ci & 7)] = __float2half_rn(v);
    } else if (i < 9 * 128 * 64 + 27 * 64) {
        int j = i - 9 * 128 * 64;
        float v = W1[j];
        g_w1d[j] = pk2(v, v);
    }
}

// ============ conv1 half-row: NP pixel-pairs starting at pair P0 ============
// Lane owns co = 2*lane, 2*lane+1. Pair accumulates (px 2p, px 2p+1) per co.
template <int P0, int NP>
__device__ __forceinline__ void conv1_half(
    char* smem, const float* s_img, int cr, int lane,
    float bv0, float bv1, int colg, bool rowok)
{
    u64 a0[NP], a1[NP];
#pragma unroll
    for (int i = 0; i < NP; i++) { a0[i] = pk2(bv0, bv0); a1[i] = pk2(bv1, bv1); }

#pragma unroll
    for (int ky = 0; ky < 3; ky++)
#pragma unroll
    for (int ci = 0; ci < 3; ci++) {
        const float4* vp = (const float4*)(s_img + ci * IPLANE + (2 * cr + ky) * IROW);
        float4 V[5];
#pragma unroll
        for (int k = 0; k < 5; k++) V[k] = vp[(P0 >> 1) + k];
        {   // kx = 0 : pairs (e_{2p}, e_{2p+1})
            ulonglong2 wq = *(const ulonglong2*)(g_w1d + ((ky * 3 + 0) * 3 + ci) * 64 + 2 * lane);
#pragma unroll
            for (int i = 0; i < NP; i++) {
                const int p = P0 + i, v = (p >> 1) - (P0 >> 1);
                u64 in = (p & 1) ? pk2(V[v].z, V[v].w) : pk2(V[v].x, V[v].y);
                fma2(a0[i], in, wq.x); fma2(a1[i], in, wq.y);
            }
        }
        {   // kx = 2 : pairs (e_{2p+1}, e_{2p+2})
            ulonglong2 wq = *(const ulonglong2*)(g_w1d + ((ky * 3 + 2) * 3 + ci) * 64 + 2 * lane);
#pragma unroll
            for (int i = 0; i < NP; i++) {
                const int p = P0 + i, v = (p >> 1) - (P0 >> 1);
                u64 in = (p & 1) ? pk2(V[v].w, V[v + 1].x) : pk2(V[v].y, V[v].z);
                fma2(a0[i], in, wq.x); fma2(a1[i], in, wq.y);
            }
        }
        {   // kx = 1 : pairs (o_{2p}, o_{2p+1})
            float4 W4[(NP + 1) / 2];
#pragma unroll
            for (int k = 0; k < (NP + 1) / 2; k++) W4[k] = vp[9 + (P0 >> 1) + k];
            ulonglong2 wq = *(const ulonglong2*)(g_w1d + ((ky * 3 + 1) * 3 + ci) * 64 + 2 * lane);
#pragma unroll
            for (int i = 0; i < NP; i++) {
                const int p = P0 + i, v = (p >> 1) - (P0 >> 1);
                u64 in = (p & 1) ? pk2(W4[v].z, W4[v].w) : pk2(W4[v].x, W4[v].y);
                fma2(a0[i], in, wq.x); fma2(a1[i], in, wq.y);
            }
        }
    }

    // store: even px -> IN_E (xe = p), odd px -> IN_O (xo = p, only p < 16)
#pragma unroll
    for (int i = 0; i < NP; i++) {
        const int p = P0 + i;
        float e0, o0, e1, o1;
        upk2(a0[i], e0, o0);
        upk2(a1[i], e1, o1);
        uint32_t he = 0, ho = 0;
        if (rowok && (colg + 2 * p) < 1152)
            he = cvtpack(fmaxf(e0, 0.f), fmaxf(e1, 0.f));
        if (p < 16 && rowok && (colg + 2 * p + 1) < 1152)
            ho = cvtpack(fmaxf(o0, 0.f), fmaxf(o1, 0.f));
        {
            const int pr = cr * 17 + p;
            *(uint32_t*)(smem + INE_OFF + pr * 128 +
                         (((lane >> 2) ^ (pr & 7)) << 4) + ((lane & 3) << 2)) = he;
        }
        if (p < 16) {
            const int pr = cr * 16 + p;
            *(uint32_t*)(smem + INO_OFF + pr * 128 +
                         (((lane >> 2) ^ (pr & 7)) << 4) + ((lane & 3) << 2)) = ho;
        }
    }
}

// ============ fused kernel: 512 thr, 16x16 conv2-out tile, 1 CTA/SM ============
__global__ __launch_bounds__(512, 1) void fused_kernel(
    const int* __restrict__ img,
    const float* __restrict__ b1,
    const float* __restrict__ b2,
    float* __restrict__ out)
{
    extern __shared__ __align__(128) char smem[];
    const uint32_t sb = smem_u32(smem);
    const int t = threadIdx.x, lane = t & 31, wid = t >> 5;
    const int bx = blockIdx.x, by = blockIdx.y;

    // Prefetch B0 (pre-swizzled weights) via cp.async.
    for (int i = t; i < 1024; i += 512)
        CP16(sb + B_OFF + i * 16, (const char*)g_w2t + i * 16);
    CP_COMMIT();

    // Stage image patch: 67 rows x 68 cols x 3 ch, /255, parity split E|O.
    float* s_img = (float*)(smem + IMG_OFF);
    const int gy0 = 64 * by, gx0 = 64 * bx;
    for (int i = t; i < 67 * 68 * 3; i += 512) {
        int c = i % 3, rem = i / 3;
        int xi = rem % 68, yi = rem / 68;
        int gy = gy0 + yi, gx = gx0 + xi;
        float v = 0.f;
        if (gy < IMG && gx < IMG)
            v = (float)img[((size_t)gy * IMG + gx) * 3 + c] * (1.f / 255.f);
        int slot = (xi & 1) ? 36 + (xi >> 1) : (xi >> 1);
        s_img[c * IPLANE + yi * IROW + slot] = v;
    }
    __syncthreads();

    // ---- conv1 phase: 33 rows over 16 warps ----
    {
        const float bv0 = __ldg(b1 + 2 * lane);
        const float bv1 = __ldg(b1 + 2 * lane + 1);
        const int colg = 32 * bx;
        const int rowg = 32 * by;
#pragma unroll 1
        for (int rr = 0; rr < 3; rr++) {
            const int cr = wid + 16 * rr;
            if (cr > 32) break;
            const bool rowok = (rowg + cr) < 1152;
            conv1_half<0, 8>(smem, s_img, cr, lane, bv0, bv1, colg, rowok);
            conv1_half<8, 9>(smem, s_img, cr, lane, bv0, bv1, colg, rowok);
        }
    }
    CP_WAIT0();
    __syncthreads();

    // ---- conv2 phase (HMMA): M=256 px (16y x 16x), N=128 co ----
    float d[2][8][4];
#pragma unroll
    for (int i = 0; i < 2; i++)
#pragma unroll
        for (int j = 0; j < 8; j++)
#pragma unroll
            for (int q = 0; q < 4; q++) d[i][j][q] = 0.f;

    const int wm = wid & 7, wn = wid >> 3;
    const int xa = lane & 15;
    const int ca = lane >> 4;
    const int nb = (lane & 7) + ((lane >> 4) << 3);
    const int cb = (lane >> 3) & 1;
    const int eB = lane & 7;
    uint32_t qB[4];
#pragma unroll
    for (int u = 0; u < 4; u++)
        qB[u] = sb + B_OFF + (uint32_t)(64 * wn + 16 * u + nb) * 128;

    for (int kk = 0; kk < 9; kk++) {
        if (kk < 8) {
            const char* src = (const char*)(g_w2t + (kk + 1) * 8192);
            uint32_t dstb = sb + B_OFF + (uint32_t)(((kk + 1) & 1) << 14);
            for (int i = t; i < 1024; i += 512)
                CP16(dstb + i * 16, src + i * 16);
            CP_COMMIT();
        }
        const int ky = kk / 3, kx = kk - ky * 3;
        uint32_t arr; int W, xoff;
        if (kx == 1) { arr = INO_OFF; W = 16; xoff = 0; }
        else         { arr = INE_OFF; W = 17; xoff = kx >> 1; }
        const int p0 = (4 * wm + ky) * W + xoff + xa;
        const int p1 = p0 + 2 * W;
        const uint32_t q0 = sb + arr + (uint32_t)p0 * 128;
        const uint32_t q1 = sb + arr + (uint32_t)p1 * 128;
        const int e0 = p0 & 7, e1 = p1 & 7;
        const uint32_t bufo = (uint32_t)((kk & 1) << 14);

#pragma unroll
        for (int s4 = 0; s4 < 4; s4++) {
            const int c = 2 * s4;
            uint32_t A0[4], A1[4];
            ldsm4(A0, q0 + (uint32_t)(((c + ca) ^ e0) << 4));
            ldsm4(A1, q1 + (uint32_t)(((c + ca) ^ e1) << 4));
            const uint32_t xb = (uint32_t)(((c + cb) ^ eB) << 4) + bufo;
#pragma unroll
            for (int u = 0; u < 4; u++) {
                uint32_t bb[4];
                ldsm4(bb, qB[u] + xb);
                mma16816(d[0][2 * u],     A0, bb[0], bb[1]);
                mma16816(d[0][2 * u + 1], A0, bb[2], bb[3]);
                mma16816(d[1][2 * u],     A1, bb[0], bb[1]);
                mma16816(d[1][2 * u + 1], A1, bb[2], bb[3]);
            }
        }
        if (kk < 8) CP_WAIT0();
        __syncthreads();
    }

    // ---- epilogue: transpose via smem (stride 260 -> conflict-free), NCHW ----
    float* s_out = (float*)smem;                  // [128 co][260]
    const int g  = lane >> 2;
    const int nq = (lane & 3) * 2;
#pragma unroll
    for (int ti = 0; ti < 2; ti++)
#pragma unroll
        for (int tj = 0; tj < 8; tj++)
#pragma unroll
            for (int rp = 0; rp < 2; rp++) {
                int m = 32 * wm + 16 * ti + g + 8 * rp;
                int n = 64 * wn + 8 * tj + nq;
                s_out[n * 260 + m]       = d[ti][tj][2 * rp];
                s_out[(n + 1) * 260 + m] = d[ti][tj][2 * rp + 1];
            }
    __syncthreads();

    const int x0 = 16 * bx, y0 = 16 * by;
    for (int e = t; e < 128 * 64; e += 512) {
        int co = e >> 6, p = (e & 63) * 4;
        int y = y0 + (p >> 4), x = x0 + (p & 15);
        float bb = __ldg(b2 + co);
        float4 v = *(float4*)(s_out + co * 260 + p);
        v.x = fmaxf(v.x + bb, 0.f);
        v.y = fmaxf(v.y + bb, 0.f);
        v.z = fmaxf(v.z + bb, 0.f);
        v.w = fmaxf(v.w + bb, 0.f);
        *(float4*)(out + ((size_t)co * H2 + y) * H2 + x) = v;
    }
}

// ======================= launch =======================
extern "C" void kernel_launch(void* const* d_in, const int* in_sizes, int n_in,
                              void* d_out, int out_size)
{
    const int*   img = (const int*)d_in[0];
    const float* W1  = (const float*)d_in[1];
    const float* b1  = (const float*)d_in[2];
    const float* W2  = (const float*)d_in[3];
    const float* b2  = (const float*)d_in[4];
    float* out = (float*)d_out;

    cudaFuncSetAttribute(fused_kernel,
                         cudaFuncAttributeMaxDynamicSharedMemorySize, SMEMT);

    prep_kernel<<<(9 * 128 * 64 + 27 * 64 + 255) / 256, 256>>>(W2, W1);
    fused_kernel<<<dim3(36, 36), 512, SMEMT>>>(img, b1, b2, out);
}

// round 6
// speedup vs baseline: 5.2753x; 1.0615x over previous
#include <cuda_runtime.h>
#include <cuda_fp16.h>
#include <cstdint>

// Fully fused conv1(FFMA2)+conv2(HMMA), 8x8 conv2-out tile per CTA,
// 256 threads, 2 CTAs/SM for cross-CTA pipe overlap (fma vs tensor).
// Full-image equivalence of the tile/crop/stitch pipeline (pad lo=0, hi=1).

#define IMG 2304
#define H2  576

typedef unsigned long long u64;

__device__ __half g_w2t[9 * 128 * 64];   // [kk][n=co][k=ci] fp16, SW128-baked
__device__ u64    g_w1d[27 * 64];        // conv1 weights dup-packed (w,w)

// smem layout (bytes)
#define INE_OFF 0                  // 17*9  = 153 units x 128B (fp16 SW128)
#define INO_OFF 19584              // 17*8  = 136 units x 128B
#define B_OFF   36992              // B double buffer 2 x 16KB
#define W1_OFF  69760              // 27*64 u64 = 13824
#define IMG_OFF 83584              // 3ch x 35rows x 60 f32 = 25200
#define SMEMT   108800
#define IROW    60                 // E[0..17] pad O@20[..37] pad S@40[..57] pad
#define IPLANE  (35 * 60)

// ---------------- helpers ----------------
__device__ __forceinline__ u64 pk2(float x, float y) {
    u64 r; asm("mov.b64 %0, {%1, %2};" : "=l"(r) : "f"(x), "f"(y)); return r;
}
__device__ __forceinline__ void upk2(u64 v, float& x, float& y) {
    asm("mov.b64 {%0, %1}, %2;" : "=f"(x), "=f"(y) : "l"(v));
}
__device__ __forceinline__ void fma2(u64& d, u64 a, u64 b) {
    asm("fma.rn.f32x2 %0, %1, %2, %0;" : "+l"(d) : "l"(a), "l"(b));
}
__device__ __forceinline__ uint32_t cvtpack(float lo, float hi) {
    uint32_t r;
    asm("cvt.rn.f16x2.f32 %0, %1, %2;" : "=r"(r) : "f"(hi), "f"(lo));
    return r;
}
__device__ __forceinline__ uint32_t smem_u32(const void* p) {
    uint32_t a;
    asm("{ .reg .u64 t; cvta.to.shared.u64 t, %1; cvt.u32.u64 %0, t; }"
        : "=r"(a) : "l"(p));
    return a;
}
__device__ __forceinline__ void ldsm4(uint32_t (&r)[4], uint32_t addr) {
    asm volatile("ldmatrix.sync.aligned.m8n8.x4.shared.b16 {%0,%1,%2,%3}, [%4];"
        : "=r"(r[0]), "=r"(r[1]), "=r"(r[2]), "=r"(r[3]) : "r"(addr));
}
__device__ __forceinline__ void mma16816(float (&d)[4], const uint32_t (&a)[4],
                                         uint32_t b0, uint32_t b1) {
    asm volatile(
        "mma.sync.aligned.m16n8k16.row.col.f32.f16.f16.f32 "
        "{%0,%1,%2,%3}, {%4,%5,%6,%7}, {%8,%9}, {%0,%1,%2,%3};"
        : "+f"(d[0]), "+f"(d[1]), "+f"(d[2]), "+f"(d[3])
        : "r"(a[0]), "r"(a[1]), "r"(a[2]), "r"(a[3]), "r"(b0), "r"(b1));
}
#define CP16(dst, src) \
    asm volatile("cp.async.ca.shared.global [%0], [%1], 16;" :: "r"(dst), "l"(src))
#define CP_COMMIT() asm volatile("cp.async.commit_group;" ::: "memory")
#define CP_WAIT0()  asm volatile("cp.async.wait_group 0;" ::: "memory")

// ============ prep: W2 -> fp16 [kk][n][k] swizzled; W1 -> dup pairs ============
__global__ void prep_kernel(const float* __restrict__ W2,
                            const float* __restrict__ W1) {
    int i = blockIdx.x * 256 + threadIdx.x;
    if (i < 9 * 128 * 64) {
        int ci = i & 63, n = (i >> 6) & 127, kk = i >> 13;
        float v = W2[(kk * 64 + ci) * 128 + n];
        int j = ci >> 3;
        g_w2t[kk * 8192 + n * 64 + ((j ^ (n & 7)) << 3) + (ci & 7)] = __float2half_rn(v);
    } else if (i < 9 * 128 * 64 + 27 * 64) {
        int j = i - 9 * 128 * 64;
        float v = W1[j];
        g_w1d[j] = pk2(v, v);
    }
}

// ============ conv1 one row r (0..16): 9 pixel-pairs, co = 2*lane, 2*lane+1 ============
__device__ __forceinline__ void conv1_row(
    char* smem, const float* s_img, const u64* s_w1, int r, int lane,
    float bv0, float bv1, int cx0, int cy0)
{
    u64 a0[9], a1[9];
#pragma unroll
    for (int p = 0; p < 9; p++) { a0[p] = pk2(bv0, bv0); a1[p] = pk2(bv1, bv1); }

#pragma unroll
    for (int ky = 0; ky < 3; ky++)
#pragma unroll
    for (int ci = 0; ci < 3; ci++) {
        const float4* vp = (const float4*)(s_img + ci * IPLANE + (2 * r + ky) * IROW);
#pragma unroll
        for (int kx = 0; kx < 3; kx++) {
            // kx=0 -> E@0, kx=1 -> O@5(f4), kx=2 -> S@10(f4); all pairs aligned.
            const int off = (kx == 0) ? 0 : (kx == 1 ? 5 : 10);
            float4 V[5];
#pragma unroll
            for (int k = 0; k < 5; k++) V[k] = vp[off + k];
            const ulonglong2 wq = *(const ulonglong2*)(
                s_w1 + ((ky * 3 + kx) * 3 + ci) * 64 + 2 * lane);
#pragma unroll
            for (int p = 0; p < 9; p++) {
                u64 in = (p & 1) ? pk2(V[p >> 1].z, V[p >> 1].w)
                                 : pk2(V[p >> 1].x, V[p >> 1].y);
                fma2(a0[p], in, wq.x);
                fma2(a1[p], in, wq.y);
            }
        }
    }

    const bool rowok = (cy0 + r) < 1152;
#pragma unroll
    for (int p = 0; p < 9; p++) {
        float e0, o0, e1, o1;
        upk2(a0[p], e0, o0);
        upk2(a1[p], e1, o1);
        uint32_t he = 0;
        if (rowok && (cx0 + 2 * p) < 1152)
            he = cvtpack(fmaxf(e0, 0.f), fmaxf(e1, 0.f));
        const int pr = r * 9 + p;
        *(uint32_t*)(smem + INE_OFF + pr * 128 +
                     (((lane >> 2) ^ (pr & 7)) << 4) + ((lane & 3) << 2)) = he;
        if (p < 8) {
            uint32_t ho = 0;
            if (rowok && (cx0 + 2 * p + 1) < 1152)
                ho = cvtpack(fmaxf(o0, 0.f), fmaxf(o1, 0.f));
            const int po = r * 8 + p;
            *(uint32_t*)(smem + INO_OFF + po * 128 +
                         (((lane >> 2) ^ (po & 7)) << 4) + ((lane & 3) << 2)) = ho;
        }
    }
}

// ============ fused kernel: 256 thr, 8x8 conv2-out tile, 2 CTAs/SM ============
__global__ __launch_bounds__(256, 2) void fused_kernel(
    const int* __restrict__ img,
    const float* __restrict__ b1,
    const float* __restrict__ b2,
    float* __restrict__ out)
{
    extern __shared__ __align__(128) char smem[];
    const uint32_t sb = smem_u32(smem);
    const int t = threadIdx.x, lane = t & 31, wid = t >> 5;
    const int bx = blockIdx.x, by = blockIdx.y;

    // Async-prefetch W1 dup pairs and B0 into smem.
    for (int i = t; i < 864; i += 256)
        CP16(sb + W1_OFF + i * 16, (const char*)g_w1d + i * 16);
    for (int i = t; i < 1024; i += 256)
        CP16(sb + B_OFF + i * 16, (const char*)g_w2t + i * 16);
    CP_COMMIT();

    // Zero image region (covers all pad slots), then stage patch.
    float* s_img = (float*)(smem + IMG_OFF);
    for (int i = t; i < 1575; i += 256)
        ((uint4*)s_img)[i] = make_uint4(0, 0, 0, 0);
    __syncthreads();

    const int iy0 = 32 * by, ix0 = 32 * bx;
    for (int i = t; i < 35 * 105; i += 256) {
        int yi = i / 105, rem = i - 105 * yi;
        int xi = rem / 3, c = rem - 3 * xi;
        int gy = iy0 + yi, gx = ix0 + xi;
        float v = 0.f;
        if (gy < IMG && gx < IMG)
            v = (float)img[((size_t)gy * IMG + gx) * 3 + c] * (1.f / 255.f);
        float* rb = s_img + c * IPLANE + yi * IROW;
        if (xi & 1) {
            rb[20 + (xi >> 1)] = v;
        } else {
            int h = xi >> 1;
            rb[h] = v;
            if (h >= 1) rb[40 + h - 1] = v;     // S[j] = E[j+1]
        }
    }
    CP_WAIT0();
    __syncthreads();

    // ---- conv1 phase: 17 rows over 8 warps ----
    {
        const u64* s_w1 = (const u64*)(smem + W1_OFF);
        const float bv0 = __ldg(b1 + 2 * lane);
        const float bv1 = __ldg(b1 + 2 * lane + 1);
        const int cx0 = 16 * bx, cy0 = 16 * by;
        conv1_row(smem, s_img, s_w1, wid,     lane, bv0, bv1, cx0, cy0);
        conv1_row(smem, s_img, s_w1, wid + 8, lane, bv0, bv1, cx0, cy0);
        if (wid == 0)
            conv1_row(smem, s_img, s_w1, 16, lane, bv0, bv1, cx0, cy0);
    }
    __syncthreads();

    // ---- conv2 phase (HMMA): M=64 px (8y x 8x), N=128 co ----
    float d[2][4][4];
#pragma unroll
    for (int i = 0; i < 2; i++)
#pragma unroll
        for (int j = 0; j < 4; j++)
#pragma unroll
            for (int q = 0; q < 4; q++) d[i][j][q] = 0.f;

    const int wm = wid >> 2, wn = wid & 3;
    const int xa = lane & 15;
    const int ca = lane >> 4;
    const int ry = xa >> 3, X = xa & 7;
    const int nb = (lane & 7) + ((lane >> 4) << 3);
    const int cb = (lane >> 3) & 1;
    const int eB = lane & 7;
    const uint32_t qB0 = sb + B_OFF + (uint32_t)(32 * wn + nb) * 128;
    const uint32_t qB1 = qB0 + 16 * 128;

    for (int kk = 0; kk < 9; kk++) {
        if (kk < 8) {
            const char* src = (const char*)(g_w2t + (kk + 1) * 8192);
            uint32_t dstb = sb + B_OFF + (uint32_t)(((kk + 1) & 1) << 14);
            for (int i = t; i < 1024; i += 256)
                CP16(dstb + i * 16, src + i * 16);
            CP_COMMIT();
        }
        const int ky = kk / 3, kx = kk - ky * 3;
        uint32_t arr; int W, xoff;
        if (kx == 1) { arr = INO_OFF; W = 8; xoff = 0; }
        else         { arr = INE_OFF; W = 9; xoff = kx >> 1; }
        const int Y0 = 4 * wm + ry;
        const int u0 = (2 * Y0 + ky) * W + X + xoff;
        const int u1 = (2 * (Y0 + 2) + ky) * W + X + xoff;
        const uint32_t q0 = sb + arr + (uint32_t)u0 * 128;
        const uint32_t q1 = sb + arr + (uint32_t)u1 * 128;
        const int e0 = u0 & 7, e1 = u1 & 7;
        const uint32_t bufo = (uint32_t)((kk & 1) << 14);

#pragma unroll
        for (int s4 = 0; s4 < 4; s4++) {
            const int cA = 2 * s4 + ca;
            uint32_t A0[4], A1[4];
            ldsm4(A0, q0 + (uint32_t)((cA ^ e0) << 4));
            ldsm4(A1, q1 + (uint32_t)((cA ^ e1) << 4));
            const uint32_t xb = (uint32_t)((((2 * s4 + cb) ^ eB) << 4)) + bufo;
            uint32_t B0[4], B1[4];
            ldsm4(B0, qB0 + xb);
            ldsm4(B1, qB1 + xb);
            mma16816(d[0][0], A0, B0[0], B0[1]);
            mma16816(d[0][1], A0, B0[2], B0[3]);
            mma16816(d[0][2], A0, B1[0], B1[1]);
            mma16816(d[0][3], A0, B1[2], B1[3]);
            mma16816(d[1][0], A1, B0[0], B0[1]);
            mma16816(d[1][1], A1, B0[2], B0[3]);
            mma16816(d[1][2], A1, B1[0], B1[1]);
            mma16816(d[1][3], A1, B1[2], B1[3]);
        }
        if (kk < 8) CP_WAIT0();
        __syncthreads();
    }

    // ---- epilogue: transpose via smem (stride 68, conflict-free), NCHW ----
    float* s_out = (float*)smem;                  // [128 co][68]
    const int g = lane >> 2;
#pragma unroll
    for (int ti = 0; ti < 2; ti++)
#pragma unroll
        for (int tn = 0; tn < 4; tn++)
#pragma unroll
            for (int rp = 0; rp < 2; rp++) {
                const int n = 32 * wn + 8 * tn + 2 * (lane & 3);
                const int m = (4 * wm + 2 * ti + rp) * 8 + g;
                s_out[n * 68 + m]       = d[ti][tn][2 * rp];
                s_out[(n + 1) * 68 + m] = d[ti][tn][2 * rp + 1];
            }
    __syncthreads();

    const int x0 = 8 * bx, y0 = 8 * by;
    for (int u = t; u < 2048; u += 256) {
        int co = u >> 4, rem = u & 15, y = rem >> 1, h = rem & 1;
        float bb = __ldg(b2 + co);
        float4 v = *(float4*)(s_out + co * 68 + y * 8 + h * 4);
        v.x = fmaxf(v.x + bb, 0.f);
        v.y = fmaxf(v.y + bb, 0.f);
        v.z = fmaxf(v.z + bb, 0.f);
        v.w = fmaxf(v.w + bb, 0.f);
        *(float4*)(out + ((size_t)co * H2 + y0 + y) * H2 + x0 + 4 * h) = v;
    }
}

// ======================= launch =======================
extern "C" void kernel_launch(void* const* d_in, const int* in_sizes, int n_in,
                              void* d_out, int out_size)
{
    const int*   img = (const int*)d_in[0];
    const float* W1  = (const float*)d_in[1];
    const float* b1  = (const float*)d_in[2];
    const float* W2  = (const float*)d_in[3];
    const float* b2  = (const float*)d_in[4];
    float* out = (float*)d_out;

    cudaFuncSetAttribute(fused_kernel,
                         cudaFuncAttributeMaxDynamicSharedMemorySize, SMEMT);

    prep_kernel<<<(9 * 128 * 64 + 27 * 64 + 255) / 256, 256>>>(W2, W1);
    fused_kernel<<<dim3(72, 72), 256, SMEMT>>>(img, b1, b2, out);
}

// round 7
// speedup vs baseline: 6.0344x; 1.1439x over previous
#include <cuda_runtime.h>
#include <cuda_fp16.h>
#include <cstdint>

// Fused conv1(FFMA2)+conv2(HMMA), 8x8 conv2-out tile per CTA, 256 threads,
// 3 CTAs/SM (smem overlay: B double-buffer reuses image+W1 region post-conv1).
// conv1 operands loaded as ulonglong2 (aligned f32 pairs) -> no packing MOVs.
// Full-image equivalence of the tile/crop/stitch pipeline (pad lo=0, hi=1).

#define IMG 2304
#define H2  576

typedef unsigned long long u64;

__device__ __half g_w2t[9 * 128 * 64];   // [kk][n=co][k=ci] fp16, SW128-baked
__device__ u64    g_w1d[27 * 64];        // conv1 weights dup-packed (w,w)

// smem layout (bytes)
#define INE_OFF 0                  // 17*9  = 153 units x 128B (fp16 SW128)
#define INO_OFF 19584              // 17*8  = 136 units x 128B -> ends 36992
#define OVL_OFF 36992
#define B_OFF   OVL_OFF            // conv2 phase: B dbuf 2 x 16384 -> 69760
#define IMG_OFF OVL_OFF            // conv1 phase: 3ch x 35rows x 60 f32 = 25200
#define W1_OFF  (OVL_OFF + 25200)  // 62192: 27*64 u64 = 13824 -> ends 76016
#define SMEMT   76016
#define IROW    60                 // E[0..17] pad O@20[..36] pad S@40[..56] pad
#define IPLANE  (35 * 60)

// ---------------- helpers ----------------
__device__ __forceinline__ u64 pk2(float x, float y) {
    u64 r; asm("mov.b64 %0, {%1, %2};" : "=l"(r) : "f"(x), "f"(y)); return r;
}
__device__ __forceinline__ void upk2(u64 v, float& x, float& y) {
    asm("mov.b64 {%0, %1}, %2;" : "=f"(x), "=f"(y) : "l"(v));
}
__device__ __forceinline__ void fma2(u64& d, u64 a, u64 b) {
    asm("fma.rn.f32x2 %0, %1, %2, %0;" : "+l"(d) : "l"(a), "l"(b));
}
__device__ __forceinline__ uint32_t cvtpack(float lo, float hi) {
    uint32_t r;
    asm("cvt.rn.f16x2.f32 %0, %1, %2;" : "=r"(r) : "f"(hi), "f"(lo));
    return r;
}
__device__ __forceinline__ uint32_t smem_u32(const void* p) {
    uint32_t a;
    asm("{ .reg .u64 t; cvta.to.shared.u64 t, %1; cvt.u32.u64 %0, t; }"
        : "=r"(a) : "l"(p));
    return a;
}
__device__ __forceinline__ void ldsm4(uint32_t (&r)[4], uint32_t addr) {
    asm volatile("ldmatrix.sync.aligned.m8n8.x4.shared.b16 {%0,%1,%2,%3}, [%4];"
        : "=r"(r[0]), "=r"(r[1]), "=r"(r[2]), "=r"(r[3]) : "r"(addr));
}
__device__ __forceinline__ void mma16816(float (&d)[4], const uint32_t (&a)[4],
                                         uint32_t b0, uint32_t b1) {
    asm volatile(
        "mma.sync.aligned.m16n8k16.row.col.f32.f16.f16.f32 "
        "{%0,%1,%2,%3}, {%4,%5,%6,%7}, {%8,%9}, {%0,%1,%2,%3};"
        : "+f"(d[0]), "+f"(d[1]), "+f"(d[2]), "+f"(d[3])
        : "r"(a[0]), "r"(a[1]), "r"(a[2]), "r"(a[3]), "r"(b0), "r"(b1));
}
#define CP16(dst, src) \
    asm volatile("cp.async.ca.shared.global [%0], [%1], 16;" :: "r"(dst), "l"(src))
#define CP_COMMIT() asm volatile("cp.async.commit_group;" ::: "memory")
#define CP_WAIT0()  asm volatile("cp.async.wait_group 0;" ::: "memory")

// ============ prep: W2 -> fp16 [kk][n][k] swizzled; W1 -> dup pairs ============
__global__ void prep_kernel(const float* __restrict__ W2,
                            const float* __restrict__ W1) {
    int i = blockIdx.x * 256 + threadIdx.x;
    if (i < 9 * 128 * 64) {
        int ci = i & 63, n = (i >> 6) & 127, kk = i >> 13;
        float v = W2[(kk * 64 + ci) * 128 + n];
        int j = ci >> 3;
        g_w2t[kk * 8192 + n * 64 + ((j ^ (n & 7)) << 3) + (ci & 7)] = __float2half_rn(v);
    } else if (i < 9 * 128 * 64 + 27 * 64) {
        int j = i - 9 * 128 * 64;
        float v = W1[j];
        g_w1d[j] = pk2(v, v);
    }
}

// ============ conv1 one row r (0..16): 9 pixel-pairs, co = 2*lane, 2*lane+1 ============
__device__ __forceinline__ void conv1_row(
    char* smem, const float* s_img, const u64* s_w1, int r, int lane,
    u64 bias0, u64 bias1, int cx0, int cy0)
{
    u64 a0[9], a1[9];
#pragma unroll
    for (int p = 0; p < 9; p++) { a0[p] = bias0; a1[p] = bias1; }

#pragma unroll
    for (int ky = 0; ky < 3; ky++)
#pragma unroll
    for (int ci = 0; ci < 3; ci++) {
        const ulonglong2* vp =
            (const ulonglong2*)(s_img + ci * IPLANE + (2 * r + ky) * IROW);
#pragma unroll
        for (int kx = 0; kx < 3; kx++) {
            const int off = (kx == 0) ? 0 : (kx == 1 ? 5 : 10);
            ulonglong2 Q[5];
#pragma unroll
            for (int k = 0; k < 5; k++) Q[k] = vp[off + k];
            const ulonglong2 wq = *(const ulonglong2*)(
                s_w1 + ((ky * 3 + kx) * 3 + ci) * 64 + 2 * lane);
#pragma unroll
            for (int p = 0; p < 9; p++) {
                const u64 in = (p & 1) ? Q[p >> 1].y : Q[p >> 1].x;
                fma2(a0[p], in, wq.x);
                fma2(a1[p], in, wq.y);
            }
        }
    }

    const bool rowok = (cy0 + r) < 1152;
#pragma unroll
    for (int p = 0; p < 9; p++) {
        float e0, o0, e1, o1;
        upk2(a0[p], e0, o0);
        upk2(a1[p], e1, o1);
        uint32_t he = 0;
        if (rowok && (cx0 + 2 * p) < 1152)
            he = cvtpack(fmaxf(e0, 0.f), fmaxf(e1, 0.f));
        const int pr = r * 9 + p;
        *(uint32_t*)(smem + INE_OFF + pr * 128 +
                     (((lane >> 2) ^ (pr & 7)) << 4) + ((lane & 3) << 2)) = he;
        if (p < 8) {
            uint32_t ho = 0;
            if (rowok && (cx0 + 2 * p + 1) < 1152)
                ho = cvtpack(fmaxf(o0, 0.f), fmaxf(o1, 0.f));
            const int po = r * 8 + p;
            *(uint32_t*)(smem + INO_OFF + po * 128 +
                         (((lane >> 2) ^ (po & 7)) << 4) + ((lane & 3) << 2)) = ho;
        }
    }
}

// ============ fused kernel: 256 thr, 8x8 conv2-out tile, 3 CTAs/SM ============
__global__ __launch_bounds__(256, 3) void fused_kernel(
    const int* __restrict__ img,
    const float* __restrict__ b1,
    const float* __restrict__ b2,
    float* __restrict__ out)
{
    extern __shared__ __align__(128) char smem[];
    const uint32_t sb = smem_u32(smem);
    const int t = threadIdx.x, lane = t & 31, wid = t >> 5;
    const int bx = blockIdx.x, by = blockIdx.y;

    // Async-prefetch W1 dup pairs into smem.
    for (int i = t; i < 864; i += 256)
        CP16(sb + W1_OFF + i * 16, (const char*)g_w1d + i * 16);
    CP_COMMIT();

    float* s_img = (float*)(smem + IMG_OFF);

    // Zero only the pad slots: per (row, ch): slots {18,19, 37,38,39, 57,58,59}.
    for (int i = t; i < 35 * 3 * 8; i += 256) {
        int s = i & 7;
        int rc = i >> 3;                // 0..104 = row*3 + c
        int slot = (s < 2) ? 18 + s : ((s < 5) ? 35 + s : 52 + s);
        int row = rc / 3, c = rc - 3 * row;
        s_img[c * IPLANE + row * IROW + slot] = 0.f;
    }

    // Stage image patch: 35 rows x 35 cols x 3 ch, /255, parity split E|O|S.
    const int iy0 = 32 * by, ix0 = 32 * bx;
    for (int row = wid; row < 35; row += 8) {
        const int gy = iy0 + row;
        const bool yok = gy < IMG;
        const int* src = img + (size_t)gy * (IMG * 3) + (size_t)ix0 * 3;
        float* rb0 = s_img + row * IROW;
        for (int j = lane; j < 105; j += 32) {
            int xi = j / 3, c = j - 3 * xi;
            float v = 0.f;
            if (yok && (ix0 + xi) < IMG)
                v = (float)src[j] * (1.f / 255.f);
            float* rb = rb0 + c * IPLANE;
            if (xi & 1) {
                rb[20 + (xi >> 1)] = v;
            } else {
                int h = xi >> 1;
                rb[h] = v;
                if (h >= 1) rb[40 + h - 1] = v;     // S[j] = E[j+1]
            }
        }
    }
    CP_WAIT0();
    __syncthreads();

    // ---- conv1 phase: 17 rows over 8 warps ----
    {
        const u64* s_w1 = (const u64*)(smem + W1_OFF);
        const u64 bias0 = pk2(__ldg(b1 + 2 * lane), __ldg(b1 + 2 * lane));
        const u64 bias1 = pk2(__ldg(b1 + 2 * lane + 1), __ldg(b1 + 2 * lane + 1));
        const int cx0 = 16 * bx, cy0 = 16 * by;
        conv1_row(smem, s_img, s_w1, wid,     lane, bias0, bias1, cx0, cy0);
        conv1_row(smem, s_img, s_w1, wid + 8, lane, bias0, bias1, cx0, cy0);
        if (wid == 0)
            conv1_row(smem, s_img, s_w1, 16, lane, bias0, bias1, cx0, cy0);
    }
    __syncthreads();   // conv1 done; IMG/W1 region dead -> B buffers may use it

    // Stage B0 (pre-swizzled weights) into overlay region.
    for (int i = t; i < 1024; i += 256)
        CP16(sb + B_OFF + i * 16, (const char*)g_w2t + i * 16);
    CP_COMMIT();
    CP_WAIT0();
    __syncthreads();

    // ---- conv2 phase (HMMA): M=64 px (8y x 8x), N=128 co ----
    float d[2][4][4];
#pragma unroll
    for (int i = 0; i < 2; i++)
#pragma unroll
        for (int j = 0; j < 4; j++)
#pragma unroll
            for (int q = 0; q < 4; q++) d[i][j][q] = 0.f;

    const int wm = wid >> 2, wn = wid & 3;
    const int xa = lane & 15;
    const int ca = lane >> 4;
    const int ry = xa >> 3, X = xa & 7;
    const int nb = (lane & 7) + ((lane >> 4) << 3);
    const int cb = (lane >> 3) & 1;
    const int eB = lane & 7;
    const uint32_t qB0 = sb + B_OFF + (uint32_t)(32 * wn + nb) * 128;
    const uint32_t qB1 = qB0 + 16 * 128;

    for (int kk = 0; kk < 9; kk++) {
        if (kk < 8) {
            const char* src = (const char*)(g_w2t + (kk + 1) * 8192);
            uint32_t dstb = sb + B_OFF + (uint32_t)(((kk + 1) & 1) << 14);
            for (int i = t; i < 1024; i += 256)
                CP16(dstb + i * 16, src + i * 16);
            CP_COMMIT();
        }
        const int ky = kk / 3, kx = kk - ky * 3;
        uint32_t arr; int W, xoff;
        if (kx == 1) { arr = INO_OFF; W = 8; xoff = 0; }
        else         { arr = INE_OFF; W = 9; xoff = kx >> 1; }
        const int Y0 = 4 * wm + ry;
        const int u0 = (2 * Y0 + ky) * W + X + xoff;
        const int u1 = (2 * (Y0 + 2) + ky) * W + X + xoff;
        const uint32_t q0 = sb + arr + (uint32_t)u0 * 128;
        const uint32_t q1 = sb + arr + (uint32_t)u1 * 128;
        const int e0 = u0 & 7, e1 = u1 & 7;
        const uint32_t bufo = (uint32_t)((kk & 1) << 14);

#pragma unroll
        for (int s4 = 0; s4 < 4; s4++) {
            const int cA = 2 * s4 + ca;
            uint32_t A0[4], A1[4];
            ldsm4(A0, q0 + (uint32_t)((cA ^ e0) << 4));
            ldsm4(A1, q1 + (uint32_t)((cA ^ e1) << 4));
            const uint32_t xb = (uint32_t)((((2 * s4 + cb) ^ eB) << 4)) + bufo;
            uint32_t B0[4], B1[4];
            ldsm4(B0, qB0 + xb);
            ldsm4(B1, qB1 + xb);
            mma16816(d[0][0], A0, B0[0], B0[1]);
            mma16816(d[0][1], A0, B0[2], B0[3]);
            mma16816(d[0][2], A0, B1[0], B1[1]);
            mma16816(d[0][3], A0, B1[2], B1[3]);
            mma16816(d[1][0], A1, B0[0], B0[1]);
            mma16816(d[1][1], A1, B0[2], B0[3]);
            mma16816(d[1][2], A1, B1[0], B1[1]);
            mma16816(d[1][3], A1, B1[2], B1[3]);
        }
        if (kk < 8) CP_WAIT0();
        __syncthreads();
    }

    // ---- epilogue: transpose via smem (stride 68, conflict-free), NCHW ----
    float* s_out = (float*)smem;                  // [128 co][68]
    const int g = lane >> 2;
#pragma unroll
    for (int ti = 0; ti < 2; ti++)
#pragma unroll
        for (int tn = 0; tn < 4; tn++)
#pragma unroll
            for (int rp = 0; rp < 2; rp++) {
                const int n = 32 * wn + 8 * tn + 2 * (lane & 3);
                const int m = (4 * wm + 2 * ti + rp) * 8 + g;
                s_out[n * 68 + m]       = d[ti][tn][2 * rp];
                s_out[(n + 1) * 68 + m] = d[ti][tn][2 * rp + 1];
            }
    __syncthreads();

    const int x0 = 8 * bx, y0 = 8 * by;
    for (int u = t; u < 2048; u += 256) {
        int co = u >> 4, rem = u & 15, y = rem >> 1, h = rem & 1;
        float bb = __ldg(b2 + co);
        float4 v = *(float4*)(s_out + co * 68 + y * 8 + h * 4);
        v.x = fmaxf(v.x + bb, 0.f);
        v.y = fmaxf(v.y + bb, 0.f);
        v.z = fmaxf(v.z + bb, 0.f);
        v.w = fmaxf(v.w + bb, 0.f);
        *(float4*)(out + ((size_t)co * H2 + y0 + y) * H2 + x0 + 4 * h) = v;
    }
}

// ======================= launch =======================
extern "C" void kernel_launch(void* const* d_in, const int* in_sizes, int n_in,
                              void* d_out, int out_size)
{
    const int*   img = (const int*)d_in[0];
    const float* W1  = (const float*)d_in[1];
    const float* b1  = (const float*)d_in[2];
    const float* W2  = (const float*)d_in[3];
    const float* b2  = (const float*)d_in[4];
    float* out = (float*)d_out;

    cudaFuncSetAttribute(fused_kernel,
                         cudaFuncAttributeMaxDynamicSharedMemorySize, SMEMT);

    prep_kernel<<<(9 * 128 * 64 + 27 * 64 + 255) / 256, 256>>>(W2, W1);
    fused_kernel<<<dim3(72, 72), 256, SMEMT>>>(img, b1, b2, out);
}

// round 8
// speedup vs baseline: 6.2684x; 1.0388x over previous
#include <cuda_runtime.h>
#include <cuda_fp16.h>
#include <cstdint>

// Fused conv1(FFMA2)+conv2(HMMA m16n8k16). CTA tile 16x8 conv2 outputs
// (M=128 px, N=128 co), 256 threads, 2 CTAs/SM.
// smem overlays: [IN tiles 71.8KB] + [img+W1 (conv1) | B dbuf (conv2)].
// Image staged in two 19-row chunks. Full-image equivalence of the
// tile/crop/stitch pipeline (SAME pad lo=0, hi=1).

#define IMG 2304
#define H2  576

typedef unsigned long long u64;

__device__ __half g_w2t[9 * 128 * 64];   // [kk][n=co][k=ci] fp16, SW128-baked
__device__ u64    g_w1d[27 * 64];        // conv1 weights dup-packed (w,w)

// smem map (bytes)
#define INE_OFF 0                    // 17 rows x 17 E-px = 289 units x 128B
#define INO_OFF 36992                // 17 rows x 16 O-px = 272 units x 128B
#define OVL_OFF 71808
#define B_OFF   OVL_OFF              // conv2: B dbuf 2 x 16384
#define IMG_OFF OVL_OFF              // conv1: 3ch x 19rows x 108 f32 = 24624
#define W1_OFF  (OVL_OFF + 24624)    // conv1: 27*64 u64 = 13824 -> end 110256
#define SMEMT   110256
#define IROW    108                  // E[0..35] | O@36[0..35] | S@72[0..35]
#define IPLANE  (19 * IROW)          // 2052 floats per channel

// ---------------- helpers ----------------
__device__ __forceinline__ u64 pk2(float x, float y) {
    u64 r; asm("mov.b64 %0, {%1, %2};" : "=l"(r) : "f"(x), "f"(y)); return r;
}
__device__ __forceinline__ void upk2(u64 v, float& x, float& y) {
    asm("mov.b64 {%0, %1}, %2;" : "=f"(x), "=f"(y) : "l"(v));
}
__device__ __forceinline__ void fma2(u64& d, u64 a, u64 b) {
    asm("fma.rn.f32x2 %0, %1, %2, %0;" : "+l"(d) : "l"(a), "l"(b));
}
__device__ __forceinline__ uint32_t cvtpack(float lo, float hi) {
    uint32_t r;
    asm("cvt.rn.f16x2.f32 %0, %1, %2;" : "=r"(r) : "f"(hi), "f"(lo));
    return r;
}
__device__ __forceinline__ uint32_t smem_u32(const void* p) {
    uint32_t a;
    asm("{ .reg .u64 t; cvta.to.shared.u64 t, %1; cvt.u32.u64 %0, t; }"
        : "=r"(a) : "l"(p));
    return a;
}
__device__ __forceinline__ void ldsm4(uint32_t (&r)[4], uint32_t addr) {
    asm volatile("ldmatrix.sync.aligned.m8n8.x4.shared.b16 {%0,%1,%2,%3}, [%4];"
        : "=r"(r[0]), "=r"(r[1]), "=r"(r[2]), "=r"(r[3]) : "r"(addr));
}
__device__ __forceinline__ void mma16816(float (&d)[4], const uint32_t (&a)[4],
                                         uint32_t b0, uint32_t b1) {
    asm volatile(
        "mma.sync.aligned.m16n8k16.row.col.f32.f16.f16.f32 "
        "{%0,%1,%2,%3}, {%4,%5,%6,%7}, {%8,%9}, {%0,%1,%2,%3};"
        : "+f"(d[0]), "+f"(d[1]), "+f"(d[2]), "+f"(d[3])
        : "r"(a[0]), "r"(a[1]), "r"(a[2]), "r"(a[3]), "r"(b0), "r"(b1));
}
#define CP16(dst, src) \
    asm volatile("cp.async.ca.shared.global [%0], [%1], 16;" :: "r"(dst), "l"(src))
#define CP_COMMIT() asm volatile("cp.async.commit_group;" ::: "memory")
#define CP_WAIT0()  asm volatile("cp.async.wait_group 0;" ::: "memory")

// ============ prep: W2 -> fp16 [kk][n][k] swizzled; W1 -> dup pairs ============
__global__ void prep_kernel(const float* __restrict__ W2,
                            const float* __restrict__ W1) {
    int i = blockIdx.x * 256 + threadIdx.x;
    if (i < 9 * 128 * 64) {
        int ci = i & 63, n = (i >> 6) & 127, kk = i >> 13;
        float v = W2[(kk * 64 + ci) * 128 + n];
        int j = ci >> 3;
        g_w2t[kk * 8192 + n * 64 + ((j ^ (n & 7)) << 3) + (ci & 7)] = __float2half_rn(v);
    } else if (i < 9 * 128 * 64 + 27 * 64) {
        int j = i - 9 * 128 * 64;
        float v = W1[j];
        g_w1d[j] = pk2(v, v);
    }
}

// ============ image staging: 19 rows x 69 cols x 3 ch, parity split E|O|S ============
__device__ __forceinline__ void stage_img(
    float* s_img, const int* __restrict__ img, int gy0, int ix0, int wid, int lane)
{
    for (int row = wid; row < 19; row += 8) {
        const int gy = gy0 + row;
        const bool yok = gy < IMG;
        const int* src = img + ((size_t)gy * IMG + ix0) * 3;
        float* rb = s_img + row * IROW;
#pragma unroll
        for (int xi0 = 0; xi0 < 96; xi0 += 32) {
            const int xi = xi0 + lane;
            if (xi >= 69) break;
            const bool ok = yok && (ix0 + xi) < IMG;
#pragma unroll
            for (int c = 0; c < 3; c++) {
                float v = ok ? (float)src[3 * xi + c] * (1.f / 255.f) : 0.f;
                float* rbc = rb + c * IPLANE;
                if (xi & 1) {
                    rbc[36 + (xi >> 1)] = v;
                } else {
                    const int h = xi >> 1;
                    rbc[h] = v;
                    if (h >= 1) rbc[72 + h - 1] = v;    // S[j] = E[j+1]
                }
            }
        }
    }
}

// ============ conv1 half-row: NP pairs from P0; co = 2*lane, 2*lane+1 ============
template <int P0, int NP>
__device__ __forceinline__ void conv1_half(
    char* smem, const float* rowbase, const u64* s_w1, int r, int lane,
    u64 bias0, u64 bias1, int cx0, bool rowok)
{
    u64 a0[NP], a1[NP];
#pragma unroll
    for (int i = 0; i < NP; i++) { a0[i] = bias0; a1[i] = bias1; }

#pragma unroll
    for (int ky = 0; ky < 3; ky++)
#pragma unroll
    for (int ci = 0; ci < 3; ci++) {
        const ulonglong2* vp =
            (const ulonglong2*)(rowbase + ci * IPLANE + ky * IROW);
#pragma unroll
        for (int kx = 0; kx < 3; kx++) {
            const int off = (kx == 0 ? 0 : (kx == 1 ? 9 : 18)) + (P0 >> 1);
            ulonglong2 Q[5];
#pragma unroll
            for (int k = 0; k < 5; k++) Q[k] = vp[off + k];
            const ulonglong2 wq = *(const ulonglong2*)(
                s_w1 + ((ky * 3 + kx) * 3 + ci) * 64 + 2 * lane);
#pragma unroll
            for (int i = 0; i < NP; i++) {
                const int p = P0 + i;
                const u64 in = (p & 1) ? Q[(p >> 1) - (P0 >> 1)].y
                                       : Q[(p >> 1) - (P0 >> 1)].x;
                fma2(a0[i], in, wq.x);
                fma2(a1[i], in, wq.y);
            }
        }
    }

#pragma unroll
    for (int i = 0; i < NP; i++) {
        const int p = P0 + i;
        float e0, o0, e1, o1;
        upk2(a0[i], e0, o0);
        upk2(a1[i], e1, o1);
        uint32_t he = 0;
        if (rowok && (cx0 + 2 * p) < 1152)
            he = cvtpack(fmaxf(e0, 0.f), fmaxf(e1, 0.f));
        const int pr = r * 17 + p;
        *(uint32_t*)(smem + INE_OFF + pr * 128 +
                     (((lane >> 2) ^ (pr & 7)) << 4) + ((lane & 3) << 2)) = he;
        if (p < 16) {
            uint32_t ho = 0;
            if (rowok && (cx0 + 2 * p + 1) < 1152)
                ho = cvtpack(fmaxf(o0, 0.f), fmaxf(o1, 0.f));
            const int po = r * 16 + p;
            *(uint32_t*)(smem + INO_OFF + po * 128 +
                         (((lane >> 2) ^ (po & 7)) << 4) + ((lane & 3) << 2)) = ho;
        }
    }
}

// ============ fused kernel: 256 thr, 16x8 conv2-out tile, 2 CTAs/SM ============
__global__ __launch_bounds__(256, 2) void fused_kernel(
    const int* __restrict__ img,
    const float* __restrict__ b1,
    const float* __restrict__ b2,
    float* __restrict__ out)
{
    extern __shared__ __align__(128) char smem[];
    const uint32_t sb = smem_u32(smem);
    const int t = threadIdx.x, lane = t & 31, wid = t >> 5;
    const int bx = blockIdx.x, by = blockIdx.y;

    // W1 dup pairs -> smem (above the image chunk region).
    for (int i = t; i < 864; i += 256)
        CP16(sb + W1_OFF + i * 16, (const char*)g_w1d + i * 16);
    CP_COMMIT();

    float* s_img = (float*)(smem + IMG_OFF);
    const int iy0 = 32 * by, ix0 = 64 * bx;   // img base (conv1 x base = 32*bx)

    // ---- chunk A: img rows 0..18 -> conv1 rows 0..7 ----
    stage_img(s_img, img, iy0, ix0, wid, lane);
    CP_WAIT0();
    __syncthreads();

    const u64* s_w1 = (const u64*)(smem + W1_OFF);
    const u64 bias0 = pk2(__ldg(b1 + 2 * lane), __ldg(b1 + 2 * lane));
    const u64 bias1 = pk2(__ldg(b1 + 2 * lane + 1), __ldg(b1 + 2 * lane + 1));
    const int cx0 = 32 * bx, cy0 = 16 * by;

    {
        const int r = wid;
        const float* rowbase = s_img + 2 * r * IROW;
        const bool rowok = (cy0 + r) < 1152;
        conv1_half<0, 9>(smem, rowbase, s_w1, r, lane, bias0, bias1, cx0, rowok);
        conv1_half<9, 8>(smem, rowbase, s_w1, r, lane, bias0, bias1, cx0, rowok);
    }
    __syncthreads();

    // ---- chunk B: img rows 16..34 -> conv1 rows 8..16 ----
    stage_img(s_img, img, iy0 + 16, ix0, wid, lane);
    __syncthreads();

    {
        const int r = 8 + wid;
        const float* rowbase = s_img + (2 * r - 16) * IROW;
        const bool rowok = (cy0 + r) < 1152;
        conv1_half<0, 9>(smem, rowbase, s_w1, r, lane, bias0, bias1, cx0, rowok);
        conv1_half<9, 8>(smem, rowbase, s_w1, r, lane, bias0, bias1, cx0, rowok);
        if (wid == 0) {
            const float* rb16 = s_img + 16 * IROW;
            const bool ok16 = (cy0 + 16) < 1152;
            conv1_half<0, 9>(smem, rb16, s_w1, 16, lane, bias0, bias1, cx0, ok16);
            conv1_half<9, 8>(smem, rb16, s_w1, 16, lane, bias0, bias1, cx0, ok16);
        }
    }
    __syncthreads();   // conv1 done; img/W1 region dead -> B dbuf may use it

    // Stage B0.
    for (int i = t; i < 1024; i += 256)
        CP16(sb + B_OFF + i * 16, (const char*)g_w2t + i * 16);
    CP_COMMIT();
    CP_WAIT0();
    __syncthreads();

    // ---- conv2 (HMMA): M=128 px (8y x 16x), N=128 co; warp = m32 x n64 ----
    float d[2][8][4];
#pragma unroll
    for (int i = 0; i < 2; i++)
#pragma unroll
        for (int j = 0; j < 8; j++)
#pragma unroll
            for (int q = 0; q < 4; q++) d[i][j][q] = 0.f;

    const int wm = wid >> 1, wn = wid & 1;
    const int xa = lane & 15;
    const int ca = lane >> 4;
    const int nb = (lane & 7) + ((lane >> 4) << 3);
    const int cb = (lane >> 3) & 1;
    const int eB = lane & 7;
    uint32_t qB[4];
#pragma unroll
    for (int g = 0; g < 4; g++)
        qB[g] = sb + B_OFF + (uint32_t)(64 * wn + 16 * g + nb) * 128;

    for (int kk = 0; kk < 9; kk++) {
        if (kk < 8) {
            const char* src = (const char*)(g_w2t + (kk + 1) * 8192);
            uint32_t dstb = sb + B_OFF + (uint32_t)(((kk + 1) & 1) << 14);
            for (int i = t; i < 1024; i += 256)
                CP16(dstb + i * 16, src + i * 16);
            CP_COMMIT();
        }
        const int ky = kk / 3, kx = kk - ky * 3;
        uint32_t arr; int W, xoff;
        if (kx == 1) { arr = INO_OFF; W = 16; xoff = 0; }
        else         { arr = INE_OFF; W = 17; xoff = kx >> 1; }
        const int u0 = (4 * wm + ky) * W + xa + xoff;
        const int u1 = (4 * wm + 2 + ky) * W + xa + xoff;
        const uint32_t q0 = sb + arr + (uint32_t)u0 * 128;
        const uint32_t q1 = sb + arr + (uint32_t)u1 * 128;
        const int e0 = u0 & 7, e1 = u1 & 7;
        const uint32_t bufo = (uint32_t)((kk & 1) << 14);

#pragma unroll
        for (int s4 = 0; s4 < 4; s4++) {
            const int cA = 2 * s4 + ca;
            uint32_t A0[4], A1[4];
            ldsm4(A0, q0 + (uint32_t)((cA ^ e0) << 4));
            ldsm4(A1, q1 + (uint32_t)((cA ^ e1) << 4));
            const uint32_t xb = (uint32_t)((((2 * s4 + cb) ^ eB) << 4)) + bufo;
#pragma unroll
            for (int g = 0; g < 4; g++) {
                uint32_t B[4];
                ldsm4(B, qB[g] + xb);
                mma16816(d[0][2 * g],     A0, B[0], B[1]);
                mma16816(d[0][2 * g + 1], A0, B[2], B[3]);
                mma16816(d[1][2 * g],     A1, B[0], B[1]);
                mma16816(d[1][2 * g + 1], A1, B[2], B[3]);
            }
        }
        if (kk < 8) CP_WAIT0();
        __syncthreads();
    }

    // ---- epilogue: transpose via smem [128 co][132], bias+ReLU, NCHW f4 ----
    float* s_out = (float*)smem;
    const int g = lane >> 2;
#pragma unroll
    for (int ti = 0; ti < 2; ti++)
#pragma unroll
        for (int tj = 0; tj < 8; tj++)
#pragma unroll
            for (int rp = 0; rp < 2; rp++) {
                const int m = (2 * wm + ti) * 16 + g + 8 * rp;
                const int n = 64 * wn + 8 * tj + 2 * (lane & 3);
                s_out[n * 132 + m]       = d[ti][tj][2 * rp];
                s_out[(n + 1) * 132 + m] = d[ti][tj][2 * rp + 1];
            }
    __syncthreads();

    const int x0g = 16 * bx, y0g = 8 * by;
    for (int u = t; u < 4096; u += 256) {
        const int co = u >> 5, j = u & 31;
        const int y = j >> 2, x = 4 * (j & 3);
        const float bb = __ldg(b2 + co);
        float4 v = *(float4*)(s_out + co * 132 + 4 * j);
        v.x = fmaxf(v.x + bb, 0.f);
        v.y = fmaxf(v.y + bb, 0.f);
        v.z = fmaxf(v.z + bb, 0.f);
        v.w = fmaxf(v.w + bb, 0.f);
        *(float4*)(out + ((size_t)co * H2 + y0g + y) * H2 + x0g + x) = v;
    }
}

// ======================= launch =======================
extern "C" void kernel_launch(void* const* d_in, const int* in_sizes, int n_in,
                              void* d_out, int out_size)
{
    const int*   img = (const int*)d_in[0];
    const float* W1  = (const float*)d_in[1];
    const float* b1  = (const float*)d_in[2];
    const float* W2  = (const float*)d_in[3];
    const float* b2  = (const float*)d_in[4];
    float* out = (float*)d_out;

    cudaFuncSetAttribute(fused_kernel,
                         cudaFuncAttributeMaxDynamicSharedMemorySize, SMEMT);

    prep_kernel<<<(9 * 128 * 64 + 27 * 64 + 255) / 256, 256>>>(W2, W1);
    fused_kernel<<<dim3(36, 72), 256, SMEMT>>>(img, b1, b2, out);
}

// round 9
// speedup vs baseline: 6.9229x; 1.1044x over previous
#include <cuda_runtime.h>
#include <cuda_fp16.h>
#include <cstdint>

// Fused conv1(FFMA2)+conv2(HMMA m16n8k16). CTA tile 16x8 conv2 outputs
// (M=128 px, N=128 co), 256 threads, 2 CTAs/SM.
// R9: single-pass conv1 rows (halved W1 smem reloads), balanced row-16 tail.

#define IMG 2304
#define H2  576

typedef unsigned long long u64;

__device__ __half g_w2t[9 * 128 * 64];   // [kk][n=co][k=ci] fp16, SW128-baked
__device__ u64    g_w1d[27 * 64];        // conv1 weights dup-packed (w,w)

// smem map (bytes)
#define INE_OFF 0                    // 17 rows x 17 E-px = 289 units x 128B
#define INO_OFF 36992                // 17 rows x 16 O-px = 272 units x 128B
#define OVL_OFF 71808
#define B_OFF   OVL_OFF              // conv2: B dbuf 2 x 16384
#define IMG_OFF OVL_OFF              // conv1: 3ch x 19rows x 108 f32 = 24624
#define W1_OFF  (OVL_OFF + 24624)    // conv1: 27*64 u64 = 13824 -> end 110256
#define SMEMT   110256
#define IROW    108                  // E[0..35] | O@36[0..35] | S@72[0..35]
#define IPLANE  (19 * IROW)          // 2052 floats per channel

// ---------------- helpers ----------------
__device__ __forceinline__ u64 pk2(float x, float y) {
    u64 r; asm("mov.b64 %0, {%1, %2};" : "=l"(r) : "f"(x), "f"(y)); return r;
}
__device__ __forceinline__ void upk2(u64 v, float& x, float& y) {
    asm("mov.b64 {%0, %1}, %2;" : "=f"(x), "=f"(y) : "l"(v));
}
__device__ __forceinline__ void fma2(u64& d, u64 a, u64 b) {
    asm("fma.rn.f32x2 %0, %1, %2, %0;" : "+l"(d) : "l"(a), "l"(b));
}
__device__ __forceinline__ uint32_t cvtpack(float lo, float hi) {
    uint32_t r;
    asm("cvt.rn.f16x2.f32 %0, %1, %2;" : "=r"(r) : "f"(hi), "f"(lo));
    return r;
}
__device__ __forceinline__ uint32_t smem_u32(const void* p) {
    uint32_t a;
    asm("{ .reg .u64 t; cvta.to.shared.u64 t, %1; cvt.u32.u64 %0, t; }"
        : "=r"(a) : "l"(p));
    return a;
}
__device__ __forceinline__ void ldsm4(uint32_t (&r)[4], uint32_t addr) {
    asm volatile("ldmatrix.sync.aligned.m8n8.x4.shared.b16 {%0,%1,%2,%3}, [%4];"
        : "=r"(r[0]), "=r"(r[1]), "=r"(r[2]), "=r"(r[3]) : "r"(addr));
}
__device__ __forceinline__ void mma16816(float (&d)[4], const uint32_t (&a)[4],
                                         uint32_t b0, uint32_t b1) {
    asm volatile(
        "mma.sync.aligned.m16n8k16.row.col.f32.f16.f16.f32 "
        "{%0,%1,%2,%3}, {%4,%5,%6,%7}, {%8,%9}, {%0,%1,%2,%3};"
        : "+f"(d[0]), "+f"(d[1]), "+f"(d[2]), "+f"(d[3])
        : "r"(a[0]), "r"(a[1]), "r"(a[2]), "r"(a[3]), "r"(b0), "r"(b1));
}
#define CP16(dst, src) \
    asm volatile("cp.async.ca.shared.global [%0], [%1], 16;" :: "r"(dst), "l"(src))
#define CP_COMMIT() asm volatile("cp.async.commit_group;" ::: "memory")
#define CP_WAIT0()  asm volatile("cp.async.wait_group 0;" ::: "memory")

// ============ prep: W2 -> fp16 [kk][n][k] swizzled; W1 -> dup pairs ============
__global__ void prep_kernel(const float* __restrict__ W2,
                            const float* __restrict__ W1) {
    int i = blockIdx.x * 256 + threadIdx.x;
    if (i < 9 * 128 * 64) {
        int ci = i & 63, n = (i >> 6) & 127, kk = i >> 13;
        float v = W2[(kk * 64 + ci) * 128 + n];
        int j = ci >> 3;
        g_w2t[kk * 8192 + n * 64 + ((j ^ (n & 7)) << 3) + (ci & 7)] = __float2half_rn(v);
    } else if (i < 9 * 128 * 64 + 27 * 64) {
        int j = i - 9 * 128 * 64;
        float v = W1[j];
        g_w1d[j] = pk2(v, v);
    }
}

// ============ image staging: 19 rows x 69 cols x 3 ch, parity split E|O|S ============
__device__ __forceinline__ void stage_img(
    float* s_img, const int* __restrict__ img, int gy0, int ix0, int wid, int lane)
{
    for (int row = wid; row < 19; row += 8) {
        const int gy = gy0 + row;
        const bool yok = gy < IMG;
        const int* src = img + ((size_t)gy * IMG + ix0) * 3;
        float* rb = s_img + row * IROW;
#pragma unroll
        for (int xi0 = 0; xi0 < 96; xi0 += 32) {
            const int xi = xi0 + lane;
            if (xi >= 69) break;
            const bool ok = yok && (ix0 + xi) < IMG;
#pragma unroll
            for (int c = 0; c < 3; c++) {
                float v = ok ? (float)src[3 * xi + c] * (1.f / 255.f) : 0.f;
                float* rbc = rb + c * IPLANE;
                if (xi & 1) {
                    rbc[36 + (xi >> 1)] = v;
                } else {
                    const int h = xi >> 1;
                    rbc[h] = v;
                    if (h >= 1) rbc[72 + h - 1] = v;    // S[j] = E[j+1]
                }
            }
        }
    }
}

// ============ conv1 store for pair p ============
__device__ __forceinline__ void conv1_store(
    char* smem, int r, int p, int lane, u64 a0, u64 a1, int cx0, bool rowok)
{
    float e0, o0, e1, o1;
    upk2(a0, e0, o0);
    upk2(a1, e1, o1);
    uint32_t he = 0;
    if (rowok && (cx0 + 2 * p) < 1152)
        he = cvtpack(fmaxf(e0, 0.f), fmaxf(e1, 0.f));
    const int pr = r * 17 + p;
    *(uint32_t*)(smem + INE_OFF + pr * 128 +
                 (((lane >> 2) ^ (pr & 7)) << 4) + ((lane & 3) << 2)) = he;
    if (p < 16) {
        uint32_t ho = 0;
        if (rowok && (cx0 + 2 * p + 1) < 1152)
            ho = cvtpack(fmaxf(o0, 0.f), fmaxf(o1, 0.f));
        const int po = r * 16 + p;
        *(uint32_t*)(smem + INO_OFF + po * 128 +
                     (((lane >> 2) ^ (po & 7)) << 4) + ((lane & 3) << 2)) = ho;
    }
}

// ============ conv1 full row (17 pairs, single weight pass) ============
__device__ __forceinline__ void conv1_row17(
    char* smem, const float* rowbase, const u64* s_w1, int r, int lane,
    u64 bias0, u64 bias1, int cx0, bool rowok)
{
    u64 a0[17], a1[17];
#pragma unroll
    for (int i = 0; i < 17; i++) { a0[i] = bias0; a1[i] = bias1; }

#pragma unroll
    for (int ky = 0; ky < 3; ky++)
#pragma unroll
    for (int ci = 0; ci < 3; ci++) {
        const ulonglong2* vp =
            (const ulonglong2*)(rowbase + ci * IPLANE + ky * IROW);
#pragma unroll
        for (int kx = 0; kx < 3; kx++) {
            const int off = (kx == 0 ? 0 : (kx == 1 ? 9 : 18));
            const ulonglong2 wq = *(const ulonglong2*)(
                s_w1 + ((ky * 3 + kx) * 3 + ci) * 64 + 2 * lane);
            ulonglong2 Q[5];
#pragma unroll
            for (int k = 0; k < 5; k++) Q[k] = vp[off + k];
#pragma unroll
            for (int p = 0; p < 10; p++) {          // p=0..9 use Q[0..4]
                const u64 in = (p & 1) ? Q[p >> 1].y : Q[p >> 1].x;
                fma2(a0[p], in, wq.x);
                fma2(a1[p], in, wq.y);
            }
#pragma unroll
            for (int k = 0; k < 4; k++) Q[k] = vp[off + 5 + k];
#pragma unroll
            for (int p = 10; p < 17; p++) {         // p=10..16 use vp[5..8]
                const u64 in = (p & 1) ? Q[(p >> 1) - 5].y : Q[(p >> 1) - 5].x;
                fma2(a0[p], in, wq.x);
                fma2(a1[p], in, wq.y);
            }
        }
    }
#pragma unroll
    for (int p = 0; p < 17; p++)
        conv1_store(smem, r, p, lane, a0[p], a1[p], cx0, rowok);
}

// ============ conv1 half row (for the split row 16) ============
template <int P0, int NP>
__device__ __forceinline__ void conv1_half(
    char* smem, const float* rowbase, const u64* s_w1, int r, int lane,
    u64 bias0, u64 bias1, int cx0, bool rowok)
{
    u64 a0[NP], a1[NP];
#pragma unroll
    for (int i = 0; i < NP; i++) { a0[i] = bias0; a1[i] = bias1; }

#pragma unroll
    for (int ky = 0; ky < 3; ky++)
#pragma unroll
    for (int ci = 0; ci < 3; ci++) {
        const ulonglong2* vp =
            (const ulonglong2*)(rowbase + ci * IPLANE + ky * IROW);
#pragma unroll
        for (int kx = 0; kx < 3; kx++) {
            const int off = (kx == 0 ? 0 : (kx == 1 ? 9 : 18)) + (P0 >> 1);
            ulonglong2 Q[5];
#pragma unroll
            for (int k = 0; k < 5; k++) Q[k] = vp[off + k];
            const ulonglong2 wq = *(const ulonglong2*)(
                s_w1 + ((ky * 3 + kx) * 3 + ci) * 64 + 2 * lane);
#pragma unroll
            for (int i = 0; i < NP; i++) {
                const int p = P0 + i;
                const u64 in = (p & 1) ? Q[(p >> 1) - (P0 >> 1)].y
                                       : Q[(p >> 1) - (P0 >> 1)].x;
                fma2(a0[i], in, wq.x);
                fma2(a1[i], in, wq.y);
            }
        }
    }
#pragma unroll
    for (int i = 0; i < NP; i++)
        conv1_store(smem, r, P0 + i, lane, a0[i], a1[i], cx0, rowok);
}

// ============ fused kernel: 256 thr, 16x8 conv2-out tile, 2 CTAs/SM ============
__global__ __launch_bounds__(256, 2) void fused_kernel(
    const int* __restrict__ img,
    const float* __restrict__ b1,
    const float* __restrict__ b2,
    float* __restrict__ out)
{
    extern __shared__ __align__(128) char smem[];
    const uint32_t sb = smem_u32(smem);
    const int t = threadIdx.x, lane = t & 31, wid = t >> 5;
    const int bx = blockIdx.x, by = blockIdx.y;

    // W1 dup pairs -> smem (above the image chunk region).
    for (int i = t; i < 864; i += 256)
        CP16(sb + W1_OFF + i * 16, (const char*)g_w1d + i * 16);
    CP_COMMIT();

    float* s_img = (float*)(smem + IMG_OFF);
    const int iy0 = 32 * by, ix0 = 64 * bx;

    // ---- chunk A: img rows 0..18 -> conv1 rows 0..7 ----
    stage_img(s_img, img, iy0, ix0, wid, lane);
    CP_WAIT0();
    __syncthreads();

    const u64* s_w1 = (const u64*)(smem + W1_OFF);
    const u64 bias0 = pk2(__ldg(b1 + 2 * lane), __ldg(b1 + 2 * lane));
    const u64 bias1 = pk2(__ldg(b1 + 2 * lane + 1), __ldg(b1 + 2 * lane + 1));
    const int cx0 = 32 * bx, cy0 = 16 * by;

    {
        const int r = wid;
        conv1_row17(smem, s_img + 2 * r * IROW, s_w1, r, lane,
                    bias0, bias1, cx0, (cy0 + r) < 1152);
    }
    __syncthreads();

    // ---- chunk B: img rows 16..34 -> conv1 rows 8..16 ----
    stage_img(s_img, img, iy0 + 16, ix0, wid, lane);
    __syncthreads();

    {
        const int r = 8 + wid;
        conv1_row17(smem, s_img + (2 * r - 16) * IROW, s_w1, r, lane,
                    bias0, bias1, cx0, (cy0 + r) < 1152);
        const float* rb16 = s_img + 16 * IROW;
        const bool ok16 = (cy0 + 16) < 1152;
        if (wid == 6)
            conv1_half<0, 9>(smem, rb16, s_w1, 16, lane, bias0, bias1, cx0, ok16);
        if (wid == 7)
            conv1_half<9, 8>(smem, rb16, s_w1, 16, lane, bias0, bias1, cx0, ok16);
    }
    __syncthreads();   // conv1 done; img/W1 region dead -> B dbuf may use it

    // Stage B0.
    for (int i = t; i < 1024; i += 256)
        CP16(sb + B_OFF + i * 16, (const char*)g_w2t + i * 16);
    CP_COMMIT();
    CP_WAIT0();
    __syncthreads();

    // ---- conv2 (HMMA): M=128 px (8y x 16x), N=128 co; warp = m32 x n64 ----
    float d[2][8][4];
#pragma unroll
    for (int i = 0; i < 2; i++)
#pragma unroll
        for (int j = 0; j < 8; j++)
#pragma unroll
            for (int q = 0; q < 4; q++) d[i][j][q] = 0.f;

    const int wm = wid >> 1, wn = wid & 1;
    const int xa = lane & 15;
    const int ca = lane >> 4;
    const int nb = (lane & 7) + ((lane >> 4) << 3);
    const int cb = (lane >> 3) & 1;
    const int eB = lane & 7;
    uint32_t qB[4];
#pragma unroll
    for (int g = 0; g < 4; g++)
        qB[g] = sb + B_OFF + (uint32_t)(64 * wn + 16 * g + nb) * 128;

    for (int kk = 0; kk < 9; kk++) {
        if (kk < 8) {
            const char* src = (const char*)(g_w2t + (kk + 1) * 8192);
            uint32_t dstb = sb + B_OFF + (uint32_t)(((kk + 1) & 1) << 14);
            for (int i = t; i < 1024; i += 256)
                CP16(dstb + i * 16, src + i * 16);
            CP_COMMIT();
        }
        const int ky = kk / 3, kx = kk - ky * 3;
        uint32_t arr; int W, xoff;
        if (kx == 1) { arr = INO_OFF; W = 16; xoff = 0; }
        else         { arr = INE_OFF; W = 17; xoff = kx >> 1; }
        const int u0 = (4 * wm + ky) * W + xa + xoff;
        const int u1 = (4 * wm + 2 + ky) * W + xa + xoff;
        const uint32_t q0 = sb + arr + (uint32_t)u0 * 128;
        const uint32_t q1 = sb + arr + (uint32_t)u1 * 128;
        const int e0 = u0 & 7, e1 = u1 & 7;
        const uint32_t bufo = (uint32_t)((kk & 1) << 14);

#pragma unroll
        for (int s4 = 0; s4 < 4; s4++) {
            const int cA = 2 * s4 + ca;
            uint32_t A0[4], A1[4];
            ldsm4(A0, q0 + (uint32_t)((cA ^ e0) << 4));
            ldsm4(A1, q1 + (uint32_t)((cA ^ e1) << 4));
            const uint32_t xb = (uint32_t)((((2 * s4 + cb) ^ eB) << 4)) + bufo;
#pragma unroll
            for (int g = 0; g < 4; g++) {
                uint32_t B[4];
                ldsm4(B, qB[g] + xb);
                mma16816(d[0][2 * g],     A0, B[0], B[1]);
                mma16816(d[0][2 * g + 1], A0, B[2], B[3]);
                mma16816(d[1][2 * g],     A1, B[0], B[1]);
                mma16816(d[1][2 * g + 1], A1, B[2], B[3]);
            }
        }
        if (kk < 8) CP_WAIT0();
        __syncthreads();
    }

    // ---- epilogue: transpose via smem [128 co][132], bias+ReLU, NCHW f4 ----
    float* s_out = (float*)smem;
    const int g = lane >> 2;
#pragma unroll
    for (int ti = 0; ti < 2; ti++)
#pragma unroll
        for (int tj = 0; tj < 8; tj++)
#pragma unroll
            for (int rp = 0; rp < 2; rp++) {
                const int m = (2 * wm + ti) * 16 + g + 8 * rp;
                const int n = 64 * wn + 8 * tj + 2 * (lane & 3);
                s_out[n * 132 + m]       = d[ti][tj][2 * rp];
                s_out[(n + 1) * 132 + m] = d[ti][tj][2 * rp + 1];
            }
    __syncthreads();

    const int x0g = 16 * bx, y0g = 8 * by;
    for (int u = t; u < 4096; u += 256) {
        const int co = u >> 5, j = u & 31;
        const int y = j >> 2, x = 4 * (j & 3);
        const float bb = __ldg(b2 + co);
        float4 v = *(float4*)(s_out + co * 132 + 4 * j);
        v.x = fmaxf(v.x + bb, 0.f);
        v.y = fmaxf(v.y + bb, 0.f);
        v.z = fmaxf(v.z + bb, 0.f);
        v.w = fmaxf(v.w + bb, 0.f);
        *(float4*)(out + ((size_t)co * H2 + y0g + y) * H2 + x0g + x) = v;
    }
}

// ======================= launch =======================
extern "C" void kernel_launch(void* const* d_in, const int* in_sizes, int n_in,
                              void* d_out, int out_size)
{
    const int*   img = (const int*)d_in[0];
    const float* W1  = (const float*)d_in[1];
    const float* b1  = (const float*)d_in[2];
    const float* W2  = (const float*)d_in[3];
    const float* b2  = (const float*)d_in[4];
    float* out = (float*)d_out;

    cudaFuncSetAttribute(fused_kernel,
                         cudaFuncAttributeMaxDynamicSharedMemorySize, SMEMT);

    prep_kernel<<<(9 * 128 * 64 + 27 * 64 + 255) / 256, 256>>>(W2, W1);
    fused_kernel<<<dim3(36, 72), 256, SMEMT>>>(img, b1, b2, out);
}